// round 5
// baseline (speedup 1.0000x reference)
#include <cuda_runtime.h>
#include <math.h>

#define Bb 64
#define Tt 50000
#define Cc 4
#define MS 4
#define Dd 160
#define PP 25
#define LL 2000          // T / PP
#define KE 25
#define KB 9
#define KP 9
#define TILE 500         // multiple of PP
#define NT (Tt / TILE)   // 100
#define HSIZE (Bb * LL * Dd)   // 20,480,000 floats of h
#define KK 100           // MS*PP GEMM depth
#define NWIN 536
#define NS0 512

// scratch: xs laid out as GEMM rows [b*L + l][m*25 + p]
__device__ float g_xs[(size_t)Bb * LL * KK];

typedef unsigned long long ull;

__device__ __forceinline__ float gelu_exact(float v) {
    return 0.5f * v * (1.0f + erff(v * 0.70710678118654752f));
}
__device__ __forceinline__ float softplus_f(float v) {
    return fmaxf(v, 0.0f) + log1pf(expf(-fabsf(v)));
}
__device__ __forceinline__ ull ffma2(ull a, ull b, ull c) {
    ull d;
    asm("fma.rn.f32x2 %0, %1, %2, %3;" : "=l"(d) : "l"(a), "l"(b), "l"(c));
    return d;
}
__device__ __forceinline__ ull mul2(ull a, ull b) {
    ull d;
    asm("mul.rn.f32x2 %0, %1, %2;" : "=l"(d) : "l"(a), "l"(b));
    return d;
}
__device__ __forceinline__ ull pack2(float x, float y) {
    ull d;
    asm("mov.b64 %0, {%1, %2};" : "=l"(d) : "f"(x), "f"(y));
    return d;
}
union F4U { float4 v; ull u[2]; };
union UF2 { ull u; float2 f; };

#define ABS2MASK 0x7FFFFFFF7FFFFFFFULL
#define NEG1P    0xBF800000BF800000ULL
#define C09P     0x3F6666663F666666ULL
#define C06P     0x3F19999A3F19999AULL
#define C02P     0x3E4CCCCD3E4CCCCDULL

// ---------------------------------------------------------------------------
// Kernel A v2: fused front pipeline, channel-paired f32x2
// ---------------------------------------------------------------------------
__global__ __launch_bounds__(256, 2) void kernelA(
    const float* __restrict__ X, const float* __restrict__ Mv,
    const float* __restrict__ w_env, const float* __restrict__ w_burst,
    const float* __restrict__ syn, const float* __restrict__ w_dw,
    const float* __restrict__ w_pw, float* __restrict__ out_mpatch)
{
    __shared__ __align__(16) ull sxr2[2][NWIN];   // raw (c0,c1)/(c2,c3) pairs
    __shared__ __align__(16) ull sdx2[2][NWIN];   // |dx| pairs
    __shared__ __align__(16) ull sS02[2][NS0];    // S0 pairs (m0,m1)/(m2,m3)
    __shared__ uchar4 smask[TILE];
    __shared__ unsigned char smt[TILE];
    __shared__ float sW[MS][Cc];
    __shared__ float sPW[MS][MS];
    __shared__ ull swe2[2][KE], swb2[2][KB], swd2[2][KP], sWsyn2[2][MS];

    const int tid  = threadIdx.x;
    const int tile = blockIdx.x;
    const int b    = blockIdx.y;
    const int t0   = tile * TILE;

    if (tid < MS) {
        float v0 = softplus_f(syn[tid * Cc + 0]);
        float v1 = softplus_f(syn[tid * Cc + 1]);
        float v2 = softplus_f(syn[tid * Cc + 2]);
        float v3 = softplus_f(syn[tid * Cc + 3]);
        float s  = fmaxf(v0 + v1 + v2 + v3, 1e-6f);
        float inv = 1.0f / s;
        sW[tid][0] = v0 * inv; sW[tid][1] = v1 * inv;
        sW[tid][2] = v2 * inv; sW[tid][3] = v3 * inv;
    }
    if (tid >= 32 && tid < 32 + MS * MS) {
        int i = tid - 32;
        sPW[i / MS][i % MS] = w_pw[i];
    }

    // ---- pass 1: raw masked x pairs + mask bytes ----
    const float4* X4 = (const float4*)(X + (size_t)b * Tt * Cc);
    const float4* M4 = (const float4*)(Mv + (size_t)b * Tt * Cc);
    for (int i = tid; i < TILE + 33; i += 256) {
        int t = t0 - 16 + i;
        float x0 = 0.f, x1 = 0.f, x2 = 0.f, x3 = 0.f;
        uchar4 mk = {0, 0, 0, 0};
        if (t >= 0 && t < Tt) {
            float4 a = X4[t], m = M4[t];
            x0 = a.x * m.x; x1 = a.y * m.y; x2 = a.z * m.z; x3 = a.w * m.w;
            mk.x = (m.x > 0.f); mk.y = (m.y > 0.f); mk.z = (m.z > 0.f); mk.w = (m.w > 0.f);
        }
        sxr2[0][i] = pack2(x0, x1);
        sxr2[1][i] = pack2(x2, x3);
        int j = i - 16;
        if (j >= 0 && j < TILE) smask[j] = mk;
    }
    __syncthreads();

    // ---- weight pair packing + pass 2: |dx| pairs ----
    if (tid < 2 * KE) {
        int cp = tid / KE, k = tid - cp * KE;
        swe2[cp][k] = pack2(w_env[(2 * cp) * KE + k], w_env[(2 * cp + 1) * KE + k]);
    } else if (tid >= 64 && tid < 64 + 2 * KB) {
        int i = tid - 64, cp = i / KB, k = i - cp * KB;
        swb2[cp][k] = pack2(w_burst[(2 * cp) * KB + k], w_burst[(2 * cp + 1) * KB + k]);
    } else if (tid >= 96 && tid < 96 + 2 * KP) {
        int i = tid - 96, p2 = i / KP, k = i - p2 * KP;
        swd2[p2][k] = pack2(w_dw[(2 * p2) * KP + k], w_dw[(2 * p2 + 1) * KP + k]);
    } else if (tid >= 128 && tid < 128 + 2 * MS) {
        int i = tid - 128, cp = i / MS, m = i - cp * MS;
        sWsyn2[cp][m] = pack2(sW[m][2 * cp], sW[m][2 * cp + 1]);
    }
    for (int i = tid; i < TILE + 33; i += 256) {
        int tg = t0 - 16 + i;
        bool v = (tg >= 1) && (tg < Tt) && (i >= 1);
        ull d0 = 0, d1 = 0;
        if (v) {
            d0 = ffma2(sxr2[0][i - 1], NEG1P, sxr2[0][i]) & ABS2MASK;
            d1 = ffma2(sxr2[1][i - 1], NEG1P, sxr2[1][i]) & ABS2MASK;
        }
        sdx2[0][i] = d0;
        sdx2[1][i] = d1;
    }
    __syncthreads();

    // ---- phase B: env/burst/xm -> S0 pairs ; 2 positions per thread ----
    if (tid < 254) {
        const int j0 = tid * 2;
        ull accm[MS][2];
        #pragma unroll
        for (int m = 0; m < MS; m++) { accm[m][0] = 0ULL; accm[m][1] = 0ULL; }

        #pragma unroll
        for (int cp = 0; cp < 2; cp++) {
            ull wr[26];
            #pragma unroll
            for (int u = 0; u < 13; u++) {
                F4U v; v.v = *(const float4*)&sxr2[cp][j0 + 2 * u];
                wr[2 * u] = v.u[0]; wr[2 * u + 1] = v.u[1];
            }
            ull xraw0 = wr[12], xraw1 = wr[13];
            #pragma unroll
            for (int u = 0; u < 26; u++) wr[u] &= ABS2MASK;

            ull env0 = 0ULL, env1 = 0ULL;
            #pragma unroll
            for (int k = 0; k < KE; k++) {
                ull w = swe2[cp][k];
                env0 = ffma2(wr[k], w, env0);
                env1 = ffma2(wr[k + 1], w, env1);
            }
            ull da[10];
            #pragma unroll
            for (int u = 0; u < 5; u++) {
                F4U v; v.v = *(const float4*)&sdx2[cp][j0 + 8 + 2 * u];
                da[2 * u] = v.u[0]; da[2 * u + 1] = v.u[1];
            }
            ull bur0 = 0ULL, bur1 = 0ULL;
            #pragma unroll
            for (int k = 0; k < KB; k++) {
                ull w = swb2[cp][k];
                bur0 = ffma2(da[k], w, bur0);
                bur1 = ffma2(da[k + 1], w, bur1);
            }
            ull xm0 = ffma2(env0, C09P, ffma2(bur0, C06P, mul2(xraw0, C02P)));
            ull xm1 = ffma2(env1, C09P, ffma2(bur1, C06P, mul2(xraw1, C02P)));
            #pragma unroll
            for (int m = 0; m < MS; m++) {
                ull w = sWsyn2[cp][m];
                accm[m][0] = ffma2(xm0, w, accm[m][0]);
                accm[m][1] = ffma2(xm1, w, accm[m][1]);
            }
        }
        #pragma unroll
        for (int p = 0; p < 2; p++) {
            int j  = j0 + p;
            int tp = t0 - 4 + j;
            bool valid = (tp >= 0 && tp < Tt);
            float s0[MS];
            #pragma unroll
            for (int m = 0; m < MS; m++) {
                UF2 u; u.u = accm[m][p];
                s0[m] = valid ? (u.f.x + u.f.y) : 0.f;
            }
            sS02[0][j] = pack2(s0[0], s0[1]);
            sS02[1][j] = pack2(s0[2], s0[3]);
        }
    }
    __syncthreads();

    // ---- phase C: dwconv9+gelu, pointwise+gelu, mask, write xs rows ----
    if (tid < 250) {
        const int i0 = tid * 2;
        float S1[2][MS];   // [pos][m]
        #pragma unroll
        for (int p2 = 0; p2 < 2; p2++) {
            ull win[10];
            #pragma unroll
            for (int u = 0; u < 5; u++) {
                F4U v; v.v = *(const float4*)&sS02[p2][i0 + 2 * u];
                win[2 * u] = v.u[0]; win[2 * u + 1] = v.u[1];
            }
            ull a0 = 0ULL, a1 = 0ULL;
            #pragma unroll
            for (int k = 0; k < KP; k++) {
                ull w = swd2[p2][k];
                a0 = ffma2(win[k], w, a0);
                a1 = ffma2(win[k + 1], w, a1);
            }
            UF2 u0, u1; u0.u = a0; u1.u = a1;
            S1[0][2 * p2]     = gelu_exact(u0.f.x);
            S1[0][2 * p2 + 1] = gelu_exact(u0.f.y);
            S1[1][2 * p2]     = gelu_exact(u1.f.x);
            S1[1][2 * p2 + 1] = gelu_exact(u1.f.y);
        }
        #pragma unroll
        for (int pos = 0; pos < 2; pos++) {
            int i = i0 + pos;
            uchar4 mk = smask[i];
            float mf0 = (float)mk.x, mf1 = (float)mk.y, mf2 = (float)mk.z, mf3 = (float)mk.w;
            int t = t0 + i;
            int l = t / PP, p = t - l * PP;
            float* dst = &g_xs[((size_t)b * LL + l) * KK + p];
            float smsum = 0.f;
            #pragma unroll
            for (int o = 0; o < MS; o++) {
                float a  = sPW[o][0] * S1[pos][0] + sPW[o][1] * S1[pos][1]
                         + sPW[o][2] * S1[pos][2] + sPW[o][3] * S1[pos][3];
                float s2 = gelu_exact(a);
                float sm = sW[o][0] * mf0 + sW[o][1] * mf1 + sW[o][2] * mf2 + sW[o][3] * mf3;
                sm = fminf(fmaxf(sm, 0.f), 1.f);
                smsum += sm;
                dst[o * PP] = s2 * sm;
            }
            smt[i] = (smsum > 0.f) ? 1 : 0;
        }
    }
    __syncthreads();

    // ---- phase D: m_patch (20 patches per tile) ----
    if (tid < TILE / PP) {
        int s = 0;
        #pragma unroll
        for (int p = 0; p < PP; p++) s += smt[tid * PP + p];
        out_mpatch[(size_t)b * LL + tile * (TILE / PP) + tid] = (s >= 3) ? 1.f : 0.f;
    }
}

// ---------------------------------------------------------------------------
// Kernel B v4: [128000 x 100] @ [100 x 160] + fused LayerNorm
//   round-2 column-paired FFMA2, but A staged pre-duplicated as (a,a) pairs:
//   inner loop = 8 LDS.64 (broadcast) + 2 LDS.128 + 32 FFMA2, zero packing.
//   block: 128 rows x 160 cols, 320 threads (16 rg x 20 dg), 8x8 per thread.
// ---------------------------------------------------------------------------
#define RB 128
#define KC 25
#define AIS 132     // sIn2 row stride (ull)
#define WS 164      // sWs row stride (float)

__global__ __launch_bounds__(320, 2) void kernelB(
    const float* __restrict__ wproj, const float* __restrict__ gamma,
    const float* __restrict__ beta, float* __restrict__ out)
{
    __shared__ __align__(16) ull sIn2[KC * AIS];    // 26.4 KB, (a,a) dup pairs
    __shared__ __align__(16) float sWs[KC * WS];    // 16.4 KB
    __shared__ float sMu[RB], sRs[RB];

    const int tid  = threadIdx.x;
    const int Row0 = blockIdx.x * RB;
    const int dg = tid % 20, rg = tid / 20;
    const int d0 = dg * 8, r0 = rg * 8;

    ull acc[8][4];
    #pragma unroll
    for (int i = 0; i < 8; i++)
        #pragma unroll
        for (int j = 0; j < 4; j++) acc[i][j] = 0ULL;

    for (int kc = 0; kc < KK / KC; kc++) {
        const int kb = kc * KC;
        __syncthreads();
        for (int i = tid; i < RB * KC; i += 320) {
            int rr = i / KC, kk = i - rr * KC;
            float a = g_xs[(size_t)(Row0 + rr) * KK + kb + kk];
            sIn2[kk * AIS + rr] = pack2(a, a);
        }
        for (int i = tid; i < Dd * KC; i += 320) {
            int d = i / KC, kk = i - d * KC;
            sWs[kk * WS + d] = wproj[d * KK + kb + kk];
        }
        __syncthreads();
        #pragma unroll 5
        for (int k = 0; k < KC; k++) {
            ull ad[8];
            #pragma unroll
            for (int ri = 0; ri < 8; ri++) ad[ri] = sIn2[k * AIS + r0 + ri];
            F4U w0, w1;
            w0.v = *(const float4*)&sWs[k * WS + d0];
            w1.v = *(const float4*)&sWs[k * WS + d0 + 4];
            #pragma unroll
            for (int r = 0; r < 8; r++) {
                acc[r][0] = ffma2(ad[r], w0.u[0], acc[r][0]);
                acc[r][1] = ffma2(ad[r], w0.u[1], acc[r][1]);
                acc[r][2] = ffma2(ad[r], w1.u[0], acc[r][2]);
                acc[r][3] = ffma2(ad[r], w1.u[1], acc[r][3]);
            }
        }
    }
    __syncthreads();

    // ---- fused LayerNorm: partial row sums from registers ----
    float* sSum = (float*)sIn2;             // [RB][20]
    float* sSq  = (float*)sIn2 + RB * 20;   // [RB][20]
    #pragma unroll
    for (int r = 0; r < 8; r++) {
        float s = 0.f, q = 0.f;
        #pragma unroll
        for (int j = 0; j < 4; j++) {
            UF2 u; u.u = acc[r][j];
            s += u.f.x + u.f.y;
            q += u.f.x * u.f.x + u.f.y * u.f.y;
        }
        sSum[(r0 + r) * 20 + dg] = s;
        sSq [(r0 + r) * 20 + dg] = q;
    }
    __syncthreads();
    if (tid < RB) {
        float s = 0.f, q = 0.f;
        #pragma unroll
        for (int j = 0; j < 20; j++) {
            s += sSum[tid * 20 + j];
            q += sSq [tid * 20 + j];
        }
        float mu  = s * (1.0f / Dd);
        float var = q * (1.0f / Dd) - mu * mu;
        sMu[tid] = mu;
        sRs[tid] = rsqrtf(var + 1e-5f);
    }
    __syncthreads();

    float gm[8], bt[8];
    #pragma unroll
    for (int j = 0; j < 8; j++) { gm[j] = gamma[d0 + j]; bt[j] = beta[d0 + j]; }

    #pragma unroll
    for (int r = 0; r < 8; r++) {
        float mu = sMu[r0 + r], rs = sRs[r0 + r];
        float v[8];
        #pragma unroll
        for (int j = 0; j < 4; j++) {
            UF2 u; u.u = acc[r][j];
            v[2 * j]     = (u.f.x - mu) * rs * gm[2 * j]     + bt[2 * j];
            v[2 * j + 1] = (u.f.y - mu) * rs * gm[2 * j + 1] + bt[2 * j + 1];
        }
        float* dst = out + (size_t)(Row0 + r0 + r) * Dd + d0;
        *(float4*)(dst)     = make_float4(v[0], v[1], v[2], v[3]);
        *(float4*)(dst + 4) = make_float4(v[4], v[5], v[6], v[7]);
    }
}

// ---------------------------------------------------------------------------
extern "C" void kernel_launch(void* const* d_in, const int* in_sizes, int n_in,
                              void* d_out, int out_size)
{
    const float* X      = (const float*)d_in[0];
    const float* M      = (const float*)d_in[1];
    const float* w_env  = (const float*)d_in[2];
    const float* w_bur  = (const float*)d_in[3];
    const float* syn    = (const float*)d_in[4];
    const float* w_dw   = (const float*)d_in[5];
    const float* w_pw   = (const float*)d_in[6];
    const float* w_proj = (const float*)d_in[7];
    const float* gamma  = (const float*)d_in[8];
    const float* beta   = (const float*)d_in[9];
    float* out = (float*)d_out;

    dim3 gA(NT, Bb);
    kernelA<<<gA, 256>>>(X, M, w_env, w_bur, syn, w_dw, w_pw, out + HSIZE);
    kernelB<<<(Bb * LL) / RB, 320>>>(w_proj, gamma, beta, out);
}

// round 7
// speedup vs baseline: 1.2772x; 1.2772x over previous
#include <cuda_runtime.h>
#include <cuda_bf16.h>
#include <math.h>
#include <cstdint>

#define Bb 64
#define Tt 50000
#define Cc 4
#define MS 4
#define Dd 160
#define PP 25
#define LL 2000          // T / PP
#define KE 25
#define KB 9
#define KP 9
#define TILE 500         // multiple of PP
#define NT (Tt / TILE)   // 100
#define HSIZE (Bb * LL * Dd)   // 20,480,000 floats of h
#define KK 100           // MS*PP GEMM depth
#define NWIN 536
#define NS0 512

// scratch: xs laid out as GEMM rows [b*L + l][m*25 + p]
__device__ float g_xs[(size_t)Bb * LL * KK];
// precomputed W b-fragments: [pass(hi/lo)][kc 7][n 20][lane 32][reg 2] u32 (bf16x2)
#define NKC 7
#define NNC 20
__device__ unsigned g_bfrag[2 * NKC * NNC * 64];

typedef unsigned long long ull;

__device__ __forceinline__ float gelu_exact(float v) {
    return 0.5f * v * (1.0f + erff(v * 0.70710678118654752f));
}
__device__ __forceinline__ float softplus_f(float v) {
    return fmaxf(v, 0.0f) + log1pf(expf(-fabsf(v)));
}
__device__ __forceinline__ ull ffma2(ull a, ull b, ull c) {
    ull d;
    asm("fma.rn.f32x2 %0, %1, %2, %3;" : "=l"(d) : "l"(a), "l"(b), "l"(c));
    return d;
}
__device__ __forceinline__ ull mul2(ull a, ull b) {
    ull d;
    asm("mul.rn.f32x2 %0, %1, %2;" : "=l"(d) : "l"(a), "l"(b));
    return d;
}
__device__ __forceinline__ ull pack2(float x, float y) {
    ull d;
    asm("mov.b64 %0, {%1, %2};" : "=l"(d) : "f"(x), "f"(y));
    return d;
}
union F4U { float4 v; ull u[2]; };
union UF2 { ull u; float2 f; };

#define ABS2MASK 0x7FFFFFFF7FFFFFFFULL
#define NEG1P    0xBF800000BF800000ULL
#define C09P     0x3F6666663F666666ULL
#define C06P     0x3F19999A3F19999AULL
#define C02P     0x3E4CCCCD3E4CCCCDULL

// ---------------------------------------------------------------------------
// Kernel A v2: fused front pipeline, channel-paired f32x2 (unchanged, passing)
// ---------------------------------------------------------------------------
__global__ __launch_bounds__(256, 2) void kernelA(
    const float* __restrict__ X, const float* __restrict__ Mv,
    const float* __restrict__ w_env, const float* __restrict__ w_burst,
    const float* __restrict__ syn, const float* __restrict__ w_dw,
    const float* __restrict__ w_pw, float* __restrict__ out_mpatch)
{
    __shared__ __align__(16) ull sxr2[2][NWIN];
    __shared__ __align__(16) ull sdx2[2][NWIN];
    __shared__ __align__(16) ull sS02[2][NS0];
    __shared__ uchar4 smask[TILE];
    __shared__ unsigned char smt[TILE];
    __shared__ float sW[MS][Cc];
    __shared__ float sPW[MS][MS];
    __shared__ ull swe2[2][KE], swb2[2][KB], swd2[2][KP], sWsyn2[2][MS];

    const int tid  = threadIdx.x;
    const int tile = blockIdx.x;
    const int b    = blockIdx.y;
    const int t0   = tile * TILE;

    if (tid < MS) {
        float v0 = softplus_f(syn[tid * Cc + 0]);
        float v1 = softplus_f(syn[tid * Cc + 1]);
        float v2 = softplus_f(syn[tid * Cc + 2]);
        float v3 = softplus_f(syn[tid * Cc + 3]);
        float s  = fmaxf(v0 + v1 + v2 + v3, 1e-6f);
        float inv = 1.0f / s;
        sW[tid][0] = v0 * inv; sW[tid][1] = v1 * inv;
        sW[tid][2] = v2 * inv; sW[tid][3] = v3 * inv;
    }
    if (tid >= 32 && tid < 32 + MS * MS) {
        int i = tid - 32;
        sPW[i / MS][i % MS] = w_pw[i];
    }

    const float4* X4 = (const float4*)(X + (size_t)b * Tt * Cc);
    const float4* M4 = (const float4*)(Mv + (size_t)b * Tt * Cc);
    for (int i = tid; i < TILE + 33; i += 256) {
        int t = t0 - 16 + i;
        float x0 = 0.f, x1 = 0.f, x2 = 0.f, x3 = 0.f;
        uchar4 mk = {0, 0, 0, 0};
        if (t >= 0 && t < Tt) {
            float4 a = X4[t], m = M4[t];
            x0 = a.x * m.x; x1 = a.y * m.y; x2 = a.z * m.z; x3 = a.w * m.w;
            mk.x = (m.x > 0.f); mk.y = (m.y > 0.f); mk.z = (m.z > 0.f); mk.w = (m.w > 0.f);
        }
        sxr2[0][i] = pack2(x0, x1);
        sxr2[1][i] = pack2(x2, x3);
        int j = i - 16;
        if (j >= 0 && j < TILE) smask[j] = mk;
    }
    __syncthreads();

    if (tid < 2 * KE) {
        int cp = tid / KE, k = tid - cp * KE;
        swe2[cp][k] = pack2(w_env[(2 * cp) * KE + k], w_env[(2 * cp + 1) * KE + k]);
    } else if (tid >= 64 && tid < 64 + 2 * KB) {
        int i = tid - 64, cp = i / KB, k = i - cp * KB;
        swb2[cp][k] = pack2(w_burst[(2 * cp) * KB + k], w_burst[(2 * cp + 1) * KB + k]);
    } else if (tid >= 96 && tid < 96 + 2 * KP) {
        int i = tid - 96, p2 = i / KP, k = i - p2 * KP;
        swd2[p2][k] = pack2(w_dw[(2 * p2) * KP + k], w_dw[(2 * p2 + 1) * KP + k]);
    } else if (tid >= 128 && tid < 128 + 2 * MS) {
        int i = tid - 128, cp = i / MS, m = i - cp * MS;
        sWsyn2[cp][m] = pack2(sW[m][2 * cp], sW[m][2 * cp + 1]);
    }
    for (int i = tid; i < TILE + 33; i += 256) {
        int tg = t0 - 16 + i;
        bool v = (tg >= 1) && (tg < Tt) && (i >= 1);
        ull d0 = 0, d1 = 0;
        if (v) {
            d0 = ffma2(sxr2[0][i - 1], NEG1P, sxr2[0][i]) & ABS2MASK;
            d1 = ffma2(sxr2[1][i - 1], NEG1P, sxr2[1][i]) & ABS2MASK;
        }
        sdx2[0][i] = d0;
        sdx2[1][i] = d1;
    }
    __syncthreads();

    if (tid < 254) {
        const int j0 = tid * 2;
        ull accm[MS][2];
        #pragma unroll
        for (int m = 0; m < MS; m++) { accm[m][0] = 0ULL; accm[m][1] = 0ULL; }

        #pragma unroll
        for (int cp = 0; cp < 2; cp++) {
            ull wr[26];
            #pragma unroll
            for (int u = 0; u < 13; u++) {
                F4U v; v.v = *(const float4*)&sxr2[cp][j0 + 2 * u];
                wr[2 * u] = v.u[0]; wr[2 * u + 1] = v.u[1];
            }
            ull xraw0 = wr[12], xraw1 = wr[13];
            #pragma unroll
            for (int u = 0; u < 26; u++) wr[u] &= ABS2MASK;

            ull env0 = 0ULL, env1 = 0ULL;
            #pragma unroll
            for (int k = 0; k < KE; k++) {
                ull w = swe2[cp][k];
                env0 = ffma2(wr[k], w, env0);
                env1 = ffma2(wr[k + 1], w, env1);
            }
            ull da[10];
            #pragma unroll
            for (int u = 0; u < 5; u++) {
                F4U v; v.v = *(const float4*)&sdx2[cp][j0 + 8 + 2 * u];
                da[2 * u] = v.u[0]; da[2 * u + 1] = v.u[1];
            }
            ull bur0 = 0ULL, bur1 = 0ULL;
            #pragma unroll
            for (int k = 0; k < KB; k++) {
                ull w = swb2[cp][k];
                bur0 = ffma2(da[k], w, bur0);
                bur1 = ffma2(da[k + 1], w, bur1);
            }
            ull xm0 = ffma2(env0, C09P, ffma2(bur0, C06P, mul2(xraw0, C02P)));
            ull xm1 = ffma2(env1, C09P, ffma2(bur1, C06P, mul2(xraw1, C02P)));
            #pragma unroll
            for (int m = 0; m < MS; m++) {
                ull w = sWsyn2[cp][m];
                accm[m][0] = ffma2(xm0, w, accm[m][0]);
                accm[m][1] = ffma2(xm1, w, accm[m][1]);
            }
        }
        #pragma unroll
        for (int p = 0; p < 2; p++) {
            int j  = j0 + p;
            int tp = t0 - 4 + j;
            bool valid = (tp >= 0 && tp < Tt);
            float s0[MS];
            #pragma unroll
            for (int m = 0; m < MS; m++) {
                UF2 u; u.u = accm[m][p];
                s0[m] = valid ? (u.f.x + u.f.y) : 0.f;
            }
            sS02[0][j] = pack2(s0[0], s0[1]);
            sS02[1][j] = pack2(s0[2], s0[3]);
        }
    }
    __syncthreads();

    if (tid < 250) {
        const int i0 = tid * 2;
        float S1[2][MS];
        #pragma unroll
        for (int p2 = 0; p2 < 2; p2++) {
            ull win[10];
            #pragma unroll
            for (int u = 0; u < 5; u++) {
                F4U v; v.v = *(const float4*)&sS02[p2][i0 + 2 * u];
                win[2 * u] = v.u[0]; win[2 * u + 1] = v.u[1];
            }
            ull a0 = 0ULL, a1 = 0ULL;
            #pragma unroll
            for (int k = 0; k < KP; k++) {
                ull w = swd2[p2][k];
                a0 = ffma2(win[k], w, a0);
                a1 = ffma2(win[k + 1], w, a1);
            }
            UF2 u0, u1; u0.u = a0; u1.u = a1;
            S1[0][2 * p2]     = gelu_exact(u0.f.x);
            S1[0][2 * p2 + 1] = gelu_exact(u0.f.y);
            S1[1][2 * p2]     = gelu_exact(u1.f.x);
            S1[1][2 * p2 + 1] = gelu_exact(u1.f.y);
        }
        #pragma unroll
        for (int pos = 0; pos < 2; pos++) {
            int i = i0 + pos;
            uchar4 mk = smask[i];
            float mf0 = (float)mk.x, mf1 = (float)mk.y, mf2 = (float)mk.z, mf3 = (float)mk.w;
            int t = t0 + i;
            int l = t / PP, p = t - l * PP;
            float* dst = &g_xs[((size_t)b * LL + l) * KK + p];
            float smsum = 0.f;
            #pragma unroll
            for (int o = 0; o < MS; o++) {
                float a  = sPW[o][0] * S1[pos][0] + sPW[o][1] * S1[pos][1]
                         + sPW[o][2] * S1[pos][2] + sPW[o][3] * S1[pos][3];
                float s2 = gelu_exact(a);
                float sm = sW[o][0] * mf0 + sW[o][1] * mf1 + sW[o][2] * mf2 + sW[o][3] * mf3;
                sm = fminf(fmaxf(sm, 0.f), 1.f);
                smsum += sm;
                dst[o * PP] = s2 * sm;
            }
            smt[i] = (smsum > 0.f) ? 1 : 0;
        }
    }
    __syncthreads();

    if (tid < TILE / PP) {
        int s = 0;
        #pragma unroll
        for (int p = 0; p < PP; p++) s += smt[tid * PP + p];
        out_mpatch[(size_t)b * LL + tile * (TILE / PP) + tid] = (s >= 3) ? 1.f : 0.f;
    }
}

// ---------------------------------------------------------------------------
// Kernel W: precompute bf16 hi/lo B-fragments of wproj for m16n8k16 HMMA.
//   B[k][n] = wproj[n][k].  frag reg rb elems: k = kc*16 + (lane&3)*2 + rb*8 (+1)
//                           n (= d) = nn*8 + (lane>>2)
// ---------------------------------------------------------------------------
__global__ void kernelW(const float* __restrict__ wproj) {
    int i = blockIdx.x * 256 + threadIdx.x;
    if (i >= 2 * NKC * NNC * 64) return;
    int bp  = i / (NKC * NNC * 64);
    int rem = i % (NKC * NNC * 64);
    int kc  = rem / (NNC * 64);
    int r2  = rem % (NNC * 64);
    int nn  = r2 / 64;
    int q   = r2 % 64;
    int lane = q >> 1, rb = q & 1;
    int d  = nn * 8 + (lane >> 2);
    int kk = kc * 16 + (lane & 3) * 2 + rb * 8;
    float w0 = (kk < KK) ? wproj[d * KK + kk] : 0.f;
    float w1 = (kk < KK) ? wproj[d * KK + kk + 1] : 0.f;
    __nv_bfloat16 h0 = __float2bfloat16_rn(w0);
    __nv_bfloat16 h1 = __float2bfloat16_rn(w1);
    unsigned v;
    if (bp == 0) {
        __nv_bfloat162 t; t.x = h0; t.y = h1;
        v = *reinterpret_cast<unsigned*>(&t);
    } else {
        __nv_bfloat162 t = __floats2bfloat162_rn(w0 - __bfloat162float(h0),
                                                 w1 - __bfloat162float(h1));
        v = *reinterpret_cast<unsigned*>(&t);
    }
    g_bfrag[i] = v;
}

// ---------------------------------------------------------------------------
// Kernel B v6: HMMA bf16-split GEMM [128000x100]@[100x160] + fused LayerNorm
//   block: 64 rows x 160 cols, 256 threads = 8 warps (4 row-groups x 2 n-halves)
//   3 passes: Ah*Bh + Al*Bh + Ah*Bl, fp32 accumulators (acc[10][4]/thread)
// ---------------------------------------------------------------------------
#define SA_U32 (2 * 4 * NKC * 128)          // 7168 u32 = 28672 B
#define SB_U32 (2 * NKC * NNC * 64)         // 17920 u32 = 71680 B
#define DYN_SMEMB ((SA_U32 + SB_U32) * 4)   // 100352 B

__device__ __forceinline__ void hmma16816(
    float& c0, float& c1, float& c2, float& c3,
    unsigned a0, unsigned a1, unsigned a2, unsigned a3,
    unsigned b0, unsigned b1)
{
    asm volatile(
        "mma.sync.aligned.m16n8k16.row.col.f32.bf16.bf16.f32 "
        "{%0,%1,%2,%3}, {%4,%5,%6,%7}, {%8,%9}, {%0,%1,%2,%3};"
        : "+f"(c0), "+f"(c1), "+f"(c2), "+f"(c3)
        : "r"(a0), "r"(a1), "r"(a2), "r"(a3), "r"(b0), "r"(b1));
}

__global__ __launch_bounds__(256, 2) void kernelB(
    const float* __restrict__ gamma, const float* __restrict__ beta,
    float* __restrict__ out)
{
    extern __shared__ __align__(16) unsigned smem[];
    unsigned* sA = smem;            // [pass2][rg4][kc7][lane32][reg4]
    unsigned* sB = smem + SA_U32;   // [pass2][kc7][nn20][lane32][rb2]
    __shared__ float sG[Dd], sBt[Dd];
    __shared__ float sSum[2][64], sSq[2][64];
    __shared__ float sMu[64], sRs[64];

    const int tid  = threadIdx.x;
    const int lane = tid & 31;
    const int wid  = tid >> 5;
    const int rg   = wid >> 1;      // row-group 0..3 (16 rows each)
    const int nh   = wid & 1;       // n-half 0..1 (10 n-chunks each)
    const int Row0 = blockIdx.x * 64;

    for (int i = tid; i < Dd; i += 256) { sG[i] = gamma[i]; sBt[i] = beta[i]; }

    // ---- stage A: g_xs fp32 -> bf16 hi/lo frag-layout smem ----
    for (int i = tid; i < 64 * 56; i += 256) {
        int r = i / 56, k2 = i - r * 56;
        int kk = 2 * k2;
        float2 v = (kk < KK) ? *(const float2*)&g_xs[(size_t)(Row0 + r) * KK + kk]
                             : make_float2(0.f, 0.f);
        __nv_bfloat16 h0 = __float2bfloat16_rn(v.x);
        __nv_bfloat16 h1 = __float2bfloat16_rn(v.y);
        unsigned hp; { __nv_bfloat162 t; t.x = h0; t.y = h1; hp = *reinterpret_cast<unsigned*>(&t); }
        unsigned lp; { __nv_bfloat162 t = __floats2bfloat162_rn(v.x - __bfloat162float(h0),
                                                                v.y - __bfloat162float(h1));
                       lp = *reinterpret_cast<unsigned*>(&t); }
        int rgw = r >> 4, rl = r & 15;
        int kc = kk >> 4, ik = kk & 15;
        int reg = (rl >> 3) + ((ik >> 3) << 1);
        int ln  = (rl & 7) * 4 + ((ik & 7) >> 1);
        int idx = ((rgw * NKC + kc) * 32 + ln) * 4 + reg;   // within one pass
        sA[idx] = hp;
        sA[4 * NKC * 128 + idx] = lp;
    }
    // ---- stage B fragments from gmem (straight copy) ----
    {
        const uint4* src = (const uint4*)g_bfrag;
        uint4* dst = (uint4*)sB;
        for (int i = tid; i < SB_U32 / 4; i += 256) dst[i] = src[i];
    }
    __syncthreads();

    // ---- mainloop ----
    float acc[10][4];
    #pragma unroll
    for (int n = 0; n < 10; n++)
        #pragma unroll
        for (int j = 0; j < 4; j++) acc[n][j] = 0.f;

    #pragma unroll
    for (int p = 0; p < 3; p++) {
        const int ap = (p == 1) ? 1 : 0;     // A: hi, lo, hi
        const int bp = (p == 2) ? 1 : 0;     // B: hi, hi, lo
        const unsigned* aBase = sA + ap * (4 * NKC * 128) + (rg * NKC) * 128;
        const unsigned* bBase = sB + bp * (NKC * NNC * 64);
        #pragma unroll
        for (int kc = 0; kc < NKC; kc++) {
            uint4 af = *(const uint4*)&aBase[kc * 128 + lane * 4];
            #pragma unroll
            for (int n = 0; n < 10; n++) {
                int nn = nh * 10 + n;
                uint2 bf = *(const uint2*)&bBase[(kc * NNC + nn) * 64 + lane * 2];
                hmma16816(acc[n][0], acc[n][1], acc[n][2], acc[n][3],
                          af.x, af.y, af.z, af.w, bf.x, bf.y);
            }
        }
    }

    // ---- LayerNorm: quad-reduce row moments ----
    float sL = 0.f, qL = 0.f, sH = 0.f, qH = 0.f;
    #pragma unroll
    for (int n = 0; n < 10; n++) {
        sL += acc[n][0] + acc[n][1];
        qL += acc[n][0] * acc[n][0] + acc[n][1] * acc[n][1];
        sH += acc[n][2] + acc[n][3];
        qH += acc[n][2] * acc[n][2] + acc[n][3] * acc[n][3];
    }
    #pragma unroll
    for (int off = 1; off <= 2; off <<= 1) {
        sL += __shfl_xor_sync(0xFFFFFFFFu, sL, off);
        qL += __shfl_xor_sync(0xFFFFFFFFu, qL, off);
        sH += __shfl_xor_sync(0xFFFFFFFFu, sH, off);
        qH += __shfl_xor_sync(0xFFFFFFFFu, qH, off);
    }
    int rl0 = rg * 16 + (lane >> 2);
    if ((lane & 3) == 0) {
        sSum[nh][rl0] = sL; sSq[nh][rl0] = qL;
        sSum[nh][rl0 + 8] = sH; sSq[nh][rl0 + 8] = qH;
    }
    __syncthreads();
    if (tid < 64) {
        float s = sSum[0][tid] + sSum[1][tid];
        float q = sSq[0][tid] + sSq[1][tid];
        float mu  = s * (1.0f / Dd);
        float var = q * (1.0f / Dd) - mu * mu;
        sMu[tid] = mu;
        sRs[tid] = rsqrtf(var + 1e-5f);
    }
    __syncthreads();

    float muL = sMu[rl0],     rsL = sRs[rl0];
    float muH = sMu[rl0 + 8], rsH = sRs[rl0 + 8];
    float* outL = out + (size_t)(Row0 + rl0) * Dd;
    float* outH = out + (size_t)(Row0 + rl0 + 8) * Dd;
    #pragma unroll
    for (int n = 0; n < 10; n++) {
        int col = (nh * 10 + n) * 8 + (lane & 3) * 2;
        float2 g = *(const float2*)&sG[col];
        float2 bt = *(const float2*)&sBt[col];
        float2 v0, v1;
        v0.x = (acc[n][0] - muL) * rsL * g.x + bt.x;
        v0.y = (acc[n][1] - muL) * rsL * g.y + bt.y;
        v1.x = (acc[n][2] - muH) * rsH * g.x + bt.x;
        v1.y = (acc[n][3] - muH) * rsH * g.y + bt.y;
        *(float2*)(outL + col) = v0;
        *(float2*)(outH + col) = v1;
    }
}

// ---------------------------------------------------------------------------
extern "C" void kernel_launch(void* const* d_in, const int* in_sizes, int n_in,
                              void* d_out, int out_size)
{
    const float* X      = (const float*)d_in[0];
    const float* M      = (const float*)d_in[1];
    const float* w_env  = (const float*)d_in[2];
    const float* w_bur  = (const float*)d_in[3];
    const float* syn    = (const float*)d_in[4];
    const float* w_dw   = (const float*)d_in[5];
    const float* w_pw   = (const float*)d_in[6];
    const float* w_proj = (const float*)d_in[7];
    const float* gamma  = (const float*)d_in[8];
    const float* beta   = (const float*)d_in[9];
    float* out = (float*)d_out;

    cudaFuncSetAttribute(kernelB, cudaFuncAttributeMaxDynamicSharedMemorySize, DYN_SMEMB);

    kernelW<<<(2 * NKC * NNC * 64 + 255) / 256, 256>>>(w_proj);
    dim3 gA(NT, Bb);
    kernelA<<<gA, 256>>>(X, M, w_env, w_bur, syn, w_dw, w_pw, out + HSIZE);
    kernelB<<<(Bb * LL) / 64, 256, DYN_SMEMB>>>(gamma, beta, out);
}

// round 8
// speedup vs baseline: 1.3106x; 1.0262x over previous
#include <cuda_runtime.h>
#include <cuda_fp16.h>
#include <math.h>
#include <cstdint>

#define Bb 64
#define Tt 50000
#define Cc 4
#define MS 4
#define Dd 160
#define PP 25
#define LL 2000          // T / PP
#define KE 25
#define KB 9
#define KP 9
#define TILE 500         // multiple of PP
#define NT (Tt / TILE)   // 100
#define HSIZE (Bb * LL * Dd)   // 20,480,000 floats of h
#define KK 100           // MS*PP GEMM depth
#define NWIN 536
#define NS0 512

// scratch: xs laid out as GEMM rows [b*L + l][m*25 + p]
__device__ float g_xs[(size_t)Bb * LL * KK];
// precomputed W Bh-fragments (fp16 hi only): [kc 7][n 20][lane 32][reg 2] u32
#define NKC 7
#define NNC 20
#define BFRAG_U32 (NKC * NNC * 64)
__device__ unsigned g_bfrag[BFRAG_U32];

typedef unsigned long long ull;

__device__ __forceinline__ float gelu_exact(float v) {
    return 0.5f * v * (1.0f + erff(v * 0.70710678118654752f));
}
__device__ __forceinline__ float softplus_f(float v) {
    return fmaxf(v, 0.0f) + log1pf(expf(-fabsf(v)));
}
__device__ __forceinline__ ull ffma2(ull a, ull b, ull c) {
    ull d;
    asm("fma.rn.f32x2 %0, %1, %2, %3;" : "=l"(d) : "l"(a), "l"(b), "l"(c));
    return d;
}
__device__ __forceinline__ ull mul2(ull a, ull b) {
    ull d;
    asm("mul.rn.f32x2 %0, %1, %2;" : "=l"(d) : "l"(a), "l"(b));
    return d;
}
__device__ __forceinline__ ull pack2(float x, float y) {
    ull d;
    asm("mov.b64 %0, {%1, %2};" : "=l"(d) : "f"(x), "f"(y));
    return d;
}
union F4U { float4 v; ull u[2]; };
union UF2 { ull u; float2 f; };

#define ABS2MASK 0x7FFFFFFF7FFFFFFFULL
#define NEG1P    0xBF800000BF800000ULL
#define C09P     0x3F6666663F666666ULL
#define C06P     0x3F19999A3F19999AULL
#define C02P     0x3E4CCCCD3E4CCCCDULL

__device__ __forceinline__ unsigned packh2(float a, float b) {
    __half2 t = __floats2half2_rn(a, b);
    return *reinterpret_cast<unsigned*>(&t);
}

// ---------------------------------------------------------------------------
// Kernel A v2: fused front pipeline, channel-paired f32x2 (unchanged, passing)
// ---------------------------------------------------------------------------
__global__ __launch_bounds__(256, 2) void kernelA(
    const float* __restrict__ X, const float* __restrict__ Mv,
    const float* __restrict__ w_env, const float* __restrict__ w_burst,
    const float* __restrict__ syn, const float* __restrict__ w_dw,
    const float* __restrict__ w_pw, float* __restrict__ out_mpatch)
{
    __shared__ __align__(16) ull sxr2[2][NWIN];
    __shared__ __align__(16) ull sdx2[2][NWIN];
    __shared__ __align__(16) ull sS02[2][NS0];
    __shared__ uchar4 smask[TILE];
    __shared__ unsigned char smt[TILE];
    __shared__ float sW[MS][Cc];
    __shared__ float sPW[MS][MS];
    __shared__ ull swe2[2][KE], swb2[2][KB], swd2[2][KP], sWsyn2[2][MS];

    const int tid  = threadIdx.x;
    const int tile = blockIdx.x;
    const int b    = blockIdx.y;
    const int t0   = tile * TILE;

    if (tid < MS) {
        float v0 = softplus_f(syn[tid * Cc + 0]);
        float v1 = softplus_f(syn[tid * Cc + 1]);
        float v2 = softplus_f(syn[tid * Cc + 2]);
        float v3 = softplus_f(syn[tid * Cc + 3]);
        float s  = fmaxf(v0 + v1 + v2 + v3, 1e-6f);
        float inv = 1.0f / s;
        sW[tid][0] = v0 * inv; sW[tid][1] = v1 * inv;
        sW[tid][2] = v2 * inv; sW[tid][3] = v3 * inv;
    }
    if (tid >= 32 && tid < 32 + MS * MS) {
        int i = tid - 32;
        sPW[i / MS][i % MS] = w_pw[i];
    }

    const float4* X4 = (const float4*)(X + (size_t)b * Tt * Cc);
    const float4* M4 = (const float4*)(Mv + (size_t)b * Tt * Cc);
    for (int i = tid; i < TILE + 33; i += 256) {
        int t = t0 - 16 + i;
        float x0 = 0.f, x1 = 0.f, x2 = 0.f, x3 = 0.f;
        uchar4 mk = {0, 0, 0, 0};
        if (t >= 0 && t < Tt) {
            float4 a = X4[t], m = M4[t];
            x0 = a.x * m.x; x1 = a.y * m.y; x2 = a.z * m.z; x3 = a.w * m.w;
            mk.x = (m.x > 0.f); mk.y = (m.y > 0.f); mk.z = (m.z > 0.f); mk.w = (m.w > 0.f);
        }
        sxr2[0][i] = pack2(x0, x1);
        sxr2[1][i] = pack2(x2, x3);
        int j = i - 16;
        if (j >= 0 && j < TILE) smask[j] = mk;
    }
    __syncthreads();

    if (tid < 2 * KE) {
        int cp = tid / KE, k = tid - cp * KE;
        swe2[cp][k] = pack2(w_env[(2 * cp) * KE + k], w_env[(2 * cp + 1) * KE + k]);
    } else if (tid >= 64 && tid < 64 + 2 * KB) {
        int i = tid - 64, cp = i / KB, k = i - cp * KB;
        swb2[cp][k] = pack2(w_burst[(2 * cp) * KB + k], w_burst[(2 * cp + 1) * KB + k]);
    } else if (tid >= 96 && tid < 96 + 2 * KP) {
        int i = tid - 96, p2 = i / KP, k = i - p2 * KP;
        swd2[p2][k] = pack2(w_dw[(2 * p2) * KP + k], w_dw[(2 * p2 + 1) * KP + k]);
    } else if (tid >= 128 && tid < 128 + 2 * MS) {
        int i = tid - 128, cp = i / MS, m = i - cp * MS;
        sWsyn2[cp][m] = pack2(sW[m][2 * cp], sW[m][2 * cp + 1]);
    }
    for (int i = tid; i < TILE + 33; i += 256) {
        int tg = t0 - 16 + i;
        bool v = (tg >= 1) && (tg < Tt) && (i >= 1);
        ull d0 = 0, d1 = 0;
        if (v) {
            d0 = ffma2(sxr2[0][i - 1], NEG1P, sxr2[0][i]) & ABS2MASK;
            d1 = ffma2(sxr2[1][i - 1], NEG1P, sxr2[1][i]) & ABS2MASK;
        }
        sdx2[0][i] = d0;
        sdx2[1][i] = d1;
    }
    __syncthreads();

    if (tid < 254) {
        const int j0 = tid * 2;
        ull accm[MS][2];
        #pragma unroll
        for (int m = 0; m < MS; m++) { accm[m][0] = 0ULL; accm[m][1] = 0ULL; }

        #pragma unroll
        for (int cp = 0; cp < 2; cp++) {
            ull wr[26];
            #pragma unroll
            for (int u = 0; u < 13; u++) {
                F4U v; v.v = *(const float4*)&sxr2[cp][j0 + 2 * u];
                wr[2 * u] = v.u[0]; wr[2 * u + 1] = v.u[1];
            }
            ull xraw0 = wr[12], xraw1 = wr[13];
            #pragma unroll
            for (int u = 0; u < 26; u++) wr[u] &= ABS2MASK;

            ull env0 = 0ULL, env1 = 0ULL;
            #pragma unroll
            for (int k = 0; k < KE; k++) {
                ull w = swe2[cp][k];
                env0 = ffma2(wr[k], w, env0);
                env1 = ffma2(wr[k + 1], w, env1);
            }
            ull da[10];
            #pragma unroll
            for (int u = 0; u < 5; u++) {
                F4U v; v.v = *(const float4*)&sdx2[cp][j0 + 8 + 2 * u];
                da[2 * u] = v.u[0]; da[2 * u + 1] = v.u[1];
            }
            ull bur0 = 0ULL, bur1 = 0ULL;
            #pragma unroll
            for (int k = 0; k < KB; k++) {
                ull w = swb2[cp][k];
                bur0 = ffma2(da[k], w, bur0);
                bur1 = ffma2(da[k + 1], w, bur1);
            }
            ull xm0 = ffma2(env0, C09P, ffma2(bur0, C06P, mul2(xraw0, C02P)));
            ull xm1 = ffma2(env1, C09P, ffma2(bur1, C06P, mul2(xraw1, C02P)));
            #pragma unroll
            for (int m = 0; m < MS; m++) {
                ull w = sWsyn2[cp][m];
                accm[m][0] = ffma2(xm0, w, accm[m][0]);
                accm[m][1] = ffma2(xm1, w, accm[m][1]);
            }
        }
        #pragma unroll
        for (int p = 0; p < 2; p++) {
            int j  = j0 + p;
            int tp = t0 - 4 + j;
            bool valid = (tp >= 0 && tp < Tt);
            float s0[MS];
            #pragma unroll
            for (int m = 0; m < MS; m++) {
                UF2 u; u.u = accm[m][p];
                s0[m] = valid ? (u.f.x + u.f.y) : 0.f;
            }
            sS02[0][j] = pack2(s0[0], s0[1]);
            sS02[1][j] = pack2(s0[2], s0[3]);
        }
    }
    __syncthreads();

    if (tid < 250) {
        const int i0 = tid * 2;
        float S1[2][MS];
        #pragma unroll
        for (int p2 = 0; p2 < 2; p2++) {
            ull win[10];
            #pragma unroll
            for (int u = 0; u < 5; u++) {
                F4U v; v.v = *(const float4*)&sS02[p2][i0 + 2 * u];
                win[2 * u] = v.u[0]; win[2 * u + 1] = v.u[1];
            }
            ull a0 = 0ULL, a1 = 0ULL;
            #pragma unroll
            for (int k = 0; k < KP; k++) {
                ull w = swd2[p2][k];
                a0 = ffma2(win[k], w, a0);
                a1 = ffma2(win[k + 1], w, a1);
            }
            UF2 u0, u1; u0.u = a0; u1.u = a1;
            S1[0][2 * p2]     = gelu_exact(u0.f.x);
            S1[0][2 * p2 + 1] = gelu_exact(u0.f.y);
            S1[1][2 * p2]     = gelu_exact(u1.f.x);
            S1[1][2 * p2 + 1] = gelu_exact(u1.f.y);
        }
        #pragma unroll
        for (int pos = 0; pos < 2; pos++) {
            int i = i0 + pos;
            uchar4 mk = smask[i];
            float mf0 = (float)mk.x, mf1 = (float)mk.y, mf2 = (float)mk.z, mf3 = (float)mk.w;
            int t = t0 + i;
            int l = t / PP, p = t - l * PP;
            float* dst = &g_xs[((size_t)b * LL + l) * KK + p];
            float smsum = 0.f;
            #pragma unroll
            for (int o = 0; o < MS; o++) {
                float a  = sPW[o][0] * S1[pos][0] + sPW[o][1] * S1[pos][1]
                         + sPW[o][2] * S1[pos][2] + sPW[o][3] * S1[pos][3];
                float s2 = gelu_exact(a);
                float sm = sW[o][0] * mf0 + sW[o][1] * mf1 + sW[o][2] * mf2 + sW[o][3] * mf3;
                sm = fminf(fmaxf(sm, 0.f), 1.f);
                smsum += sm;
                dst[o * PP] = s2 * sm;
            }
            smt[i] = (smsum > 0.f) ? 1 : 0;
        }
    }
    __syncthreads();

    if (tid < TILE / PP) {
        int s = 0;
        #pragma unroll
        for (int p = 0; p < PP; p++) s += smt[tid * PP + p];
        out_mpatch[(size_t)b * LL + tile * (TILE / PP) + tid] = (s >= 3) ? 1.f : 0.f;
    }
}

// ---------------------------------------------------------------------------
// Kernel W: precompute fp16 Bh-fragments of wproj for m16n8k16 HMMA.
//   frag reg rb elems: k = kc*16 + (lane&3)*2 + rb*8 (+1); n (= d) = nn*8 + lane>>2
// ---------------------------------------------------------------------------
__global__ void kernelW(const float* __restrict__ wproj) {
    int i = blockIdx.x * 256 + threadIdx.x;
    if (i >= BFRAG_U32) return;
    int kc  = i / (NNC * 64);
    int r2  = i % (NNC * 64);
    int nn  = r2 / 64;
    int q   = r2 % 64;
    int lane = q >> 1, rb = q & 1;
    int d  = nn * 8 + (lane >> 2);
    int kk = kc * 16 + (lane & 3) * 2 + rb * 8;
    float w0 = (kk < KK) ? wproj[d * KK + kk] : 0.f;
    float w1 = (kk < KK) ? wproj[d * KK + kk + 1] : 0.f;
    g_bfrag[i] = packh2(w0, w1);
}

// ---------------------------------------------------------------------------
// Kernel B v7: HMMA fp16 2-pass GEMM [128000x100]@[100x160] + fused LayerNorm
//   block: 64 rows x 160 cols, 256 threads = 8 warps (4 row-groups x 2 n-halves)
//   2 passes: Ah*Bh + Al*Bh (fp16 split of A; B kept fp16 hi only)
// ---------------------------------------------------------------------------
#define SA_U32 (2 * 4 * NKC * 128)          // 7168 u32 = 28672 B
#define SB_U32 BFRAG_U32                    // 8960 u32 = 35840 B
#define DYN_SMEMB ((SA_U32 + SB_U32) * 4)   // 64512 B

__device__ __forceinline__ void hmma16816(
    float& c0, float& c1, float& c2, float& c3,
    unsigned a0, unsigned a1, unsigned a2, unsigned a3,
    unsigned b0, unsigned b1)
{
    asm volatile(
        "mma.sync.aligned.m16n8k16.row.col.f32.f16.f16.f32 "
        "{%0,%1,%2,%3}, {%4,%5,%6,%7}, {%8,%9}, {%0,%1,%2,%3};"
        : "+f"(c0), "+f"(c1), "+f"(c2), "+f"(c3)
        : "r"(a0), "r"(a1), "r"(a2), "r"(a3), "r"(b0), "r"(b1));
}

__global__ __launch_bounds__(256, 2) void kernelB(
    const float* __restrict__ gamma, const float* __restrict__ beta,
    float* __restrict__ out)
{
    extern __shared__ __align__(16) unsigned smem[];
    unsigned* sA = smem;            // [pass2][rg4][kc7][lane32][reg4]
    unsigned* sB = smem + SA_U32;   // [kc7][nn20][lane32][rb2]
    __shared__ float sG[Dd], sBt[Dd];
    __shared__ float sSum[2][64], sSq[2][64];
    __shared__ float sMu[64], sRs[64];

    const int tid  = threadIdx.x;
    const int lane = tid & 31;
    const int wid  = tid >> 5;
    const int rg   = wid >> 1;      // row-group 0..3 (16 rows each)
    const int nh   = wid & 1;       // n-half 0..1 (10 n-chunks each)
    const int Row0 = blockIdx.x * 64;

    for (int i = tid; i < Dd; i += 256) { sG[i] = gamma[i]; sBt[i] = beta[i]; }

    // ---- stage A: g_xs fp32 -> fp16 hi/lo frag-layout smem ----
    for (int i = tid; i < 64 * 56; i += 256) {
        int r = i / 56, k2 = i - r * 56;
        int kk = 2 * k2;
        float2 v = (kk < KK) ? *(const float2*)&g_xs[(size_t)(Row0 + r) * KK + kk]
                             : make_float2(0.f, 0.f);
        __half h0 = __float2half_rn(v.x);
        __half h1 = __float2half_rn(v.y);
        unsigned hp; { __half2 t; t.x = h0; t.y = h1; hp = *reinterpret_cast<unsigned*>(&t); }
        unsigned lp = packh2(v.x - __half2float(h0), v.y - __half2float(h1));
        int rgw = r >> 4, rl = r & 15;
        int kc = kk >> 4, ik = kk & 15;
        int reg = (rl >> 3) + ((ik >> 3) << 1);
        int ln  = (rl & 7) * 4 + ((ik & 7) >> 1);
        int idx = ((rgw * NKC + kc) * 32 + ln) * 4 + reg;   // within one pass
        sA[idx] = hp;
        sA[4 * NKC * 128 + idx] = lp;
    }
    // ---- stage B fragments from gmem (straight copy, L2-hot) ----
    {
        const uint4* src = (const uint4*)g_bfrag;
        uint4* dst = (uint4*)sB;
        for (int i = tid; i < SB_U32 / 4; i += 256) dst[i] = src[i];
    }
    __syncthreads();

    // ---- mainloop: 2 passes ----
    float acc[10][4];
    #pragma unroll
    for (int n = 0; n < 10; n++)
        #pragma unroll
        for (int j = 0; j < 4; j++) acc[n][j] = 0.f;

    #pragma unroll
    for (int p = 0; p < 2; p++) {
        const unsigned* aBase = sA + p * (4 * NKC * 128) + (rg * NKC) * 128;
        #pragma unroll
        for (int kc = 0; kc < NKC; kc++) {
            uint4 af = *(const uint4*)&aBase[kc * 128 + lane * 4];
            #pragma unroll
            for (int n = 0; n < 10; n++) {
                int nn = nh * 10 + n;
                uint2 bf = *(const uint2*)&sB[(kc * NNC + nn) * 64 + lane * 2];
                hmma16816(acc[n][0], acc[n][1], acc[n][2], acc[n][3],
                          af.x, af.y, af.z, af.w, bf.x, bf.y);
            }
        }
    }

    // ---- LayerNorm: quad-reduce row moments ----
    float sL = 0.f, qL = 0.f, sH = 0.f, qH = 0.f;
    #pragma unroll
    for (int n = 0; n < 10; n++) {
        sL += acc[n][0] + acc[n][1];
        qL += acc[n][0] * acc[n][0] + acc[n][1] * acc[n][1];
        sH += acc[n][2] + acc[n][3];
        qH += acc[n][2] * acc[n][2] + acc[n][3] * acc[n][3];
    }
    #pragma unroll
    for (int off = 1; off <= 2; off <<= 1) {
        sL += __shfl_xor_sync(0xFFFFFFFFu, sL, off);
        qL += __shfl_xor_sync(0xFFFFFFFFu, qL, off);
        sH += __shfl_xor_sync(0xFFFFFFFFu, sH, off);
        qH += __shfl_xor_sync(0xFFFFFFFFu, qH, off);
    }
    int rl0 = rg * 16 + (lane >> 2);
    if ((lane & 3) == 0) {
        sSum[nh][rl0] = sL; sSq[nh][rl0] = qL;
        sSum[nh][rl0 + 8] = sH; sSq[nh][rl0 + 8] = qH;
    }
    __syncthreads();
    if (tid < 64) {
        float s = sSum[0][tid] + sSum[1][tid];
        float q = sSq[0][tid] + sSq[1][tid];
        float mu  = s * (1.0f / Dd);
        float var = q * (1.0f / Dd) - mu * mu;
        sMu[tid] = mu;
        sRs[tid] = rsqrtf(var + 1e-5f);
    }
    __syncthreads();

    float muL = sMu[rl0],     rsL = sRs[rl0];
    float muH = sMu[rl0 + 8], rsH = sRs[rl0 + 8];
    float* outL = out + (size_t)(Row0 + rl0) * Dd;
    float* outH = out + (size_t)(Row0 + rl0 + 8) * Dd;
    #pragma unroll
    for (int n = 0; n < 10; n++) {
        int col = (nh * 10 + n) * 8 + (lane & 3) * 2;
        float2 g = *(const float2*)&sG[col];
        float2 bt = *(const float2*)&sBt[col];
        float2 v0, v1;
        v0.x = (acc[n][0] - muL) * rsL * g.x + bt.x;
        v0.y = (acc[n][1] - muL) * rsL * g.y + bt.y;
        v1.x = (acc[n][2] - muH) * rsH * g.x + bt.x;
        v1.y = (acc[n][3] - muH) * rsH * g.y + bt.y;
        *(float2*)(outL + col) = v0;
        *(float2*)(outH + col) = v1;
    }
}

// ---------------------------------------------------------------------------
extern "C" void kernel_launch(void* const* d_in, const int* in_sizes, int n_in,
                              void* d_out, int out_size)
{
    const float* X      = (const float*)d_in[0];
    const float* M      = (const float*)d_in[1];
    const float* w_env  = (const float*)d_in[2];
    const float* w_bur  = (const float*)d_in[3];
    const float* syn    = (const float*)d_in[4];
    const float* w_dw   = (const float*)d_in[5];
    const float* w_pw   = (const float*)d_in[6];
    const float* w_proj = (const float*)d_in[7];
    const float* gamma  = (const float*)d_in[8];
    const float* beta   = (const float*)d_in[9];
    float* out = (float*)d_out;

    cudaFuncSetAttribute(kernelB, cudaFuncAttributeMaxDynamicSharedMemorySize, DYN_SMEMB);

    kernelW<<<(BFRAG_U32 + 255) / 256, 256>>>(w_proj);
    dim3 gA(NT, Bb);
    kernelA<<<gA, 256>>>(X, M, w_env, w_bur, syn, w_dw, w_pw, out + HSIZE);
    kernelB<<<(Bb * LL) / 64, 256, DYN_SMEMB>>>(gamma, beta, out);
}

// round 9
// speedup vs baseline: 1.3493x; 1.0295x over previous
#include <cuda_runtime.h>
#include <cuda_fp16.h>
#include <math.h>
#include <cstdint>

#define Bb 64
#define Tt 50000
#define Cc 4
#define MS 4
#define Dd 160
#define PP 25
#define KE 25
#define KB 9
#define KP 9
#define LL 2000
#define TILE 1000
#define NT (Tt / TILE)          // 50
#define RPT (TILE / PP)         // 40 rows per tile
#define HSIZE (Bb * LL * Dd)
#define KK 100
#define NWIN 1036
#define NS0 1012
#define XST 120                 // sX stride in halves (k pad 112 + 8)

// precomputed W Bh-fragments (fp16): [kc 7][nn 20][lane 32][rb 2] u32
#define NKC 7
#define NNC 20
#define BFRAG_U32 (NKC * NNC * 64)
__device__ unsigned g_bfrag[BFRAG_U32];

typedef unsigned long long ull;

__device__ __forceinline__ float gelu_exact(float v) {
    return 0.5f * v * (1.0f + erff(v * 0.70710678118654752f));
}
__device__ __forceinline__ float softplus_f(float v) {
    return fmaxf(v, 0.0f) + log1pf(expf(-fabsf(v)));
}
__device__ __forceinline__ ull ffma2(ull a, ull b, ull c) {
    ull d;
    asm("fma.rn.f32x2 %0, %1, %2, %3;" : "=l"(d) : "l"(a), "l"(b), "l"(c));
    return d;
}
__device__ __forceinline__ ull mul2(ull a, ull b) {
    ull d;
    asm("mul.rn.f32x2 %0, %1, %2;" : "=l"(d) : "l"(a), "l"(b));
    return d;
}
__device__ __forceinline__ ull pack2(float x, float y) {
    ull d;
    asm("mov.b64 %0, {%1, %2};" : "=l"(d) : "f"(x), "f"(y));
    return d;
}
union F4U { float4 v; ull u[2]; };
union UF2 { ull u; float2 f; };

#define ABS2MASK 0x7FFFFFFF7FFFFFFFULL
#define NEG1P    0xBF800000BF800000ULL
#define C09P     0x3F6666663F666666ULL
#define C06P     0x3F19999A3F19999AULL
#define C02P     0x3E4CCCCD3E4CCCCDULL

__device__ __forceinline__ unsigned packh2(float a, float b) {
    __half2 t = __floats2half2_rn(a, b);
    return *reinterpret_cast<unsigned*>(&t);
}

__device__ __forceinline__ void hmma16816(
    float& c0, float& c1, float& c2, float& c3,
    unsigned a0, unsigned a1, unsigned a2, unsigned a3,
    unsigned b0, unsigned b1)
{
    asm volatile(
        "mma.sync.aligned.m16n8k16.row.col.f32.f16.f16.f32 "
        "{%0,%1,%2,%3}, {%4,%5,%6,%7}, {%8,%9}, {%0,%1,%2,%3};"
        : "+f"(c0), "+f"(c1), "+f"(c2), "+f"(c3)
        : "r"(a0), "r"(a1), "r"(a2), "r"(a3), "r"(b0), "r"(b1));
}

// ---------------------------------------------------------------------------
// Kernel W: precompute fp16 B-fragments of wproj for m16n8k16 HMMA.
// ---------------------------------------------------------------------------
__global__ void kernelW(const float* __restrict__ wproj) {
    int i = blockIdx.x * 256 + threadIdx.x;
    if (i >= BFRAG_U32) return;
    int kc  = i / (NNC * 64);
    int r2  = i % (NNC * 64);
    int nn  = r2 / 64;
    int q   = r2 % 64;
    int lane = q >> 1, rb = q & 1;
    int d  = nn * 8 + (lane >> 2);
    int kk = kc * 16 + (lane & 3) * 2 + rb * 8;
    float w0 = (kk < KK) ? wproj[d * KK + kk] : 0.f;
    float w1 = (kk < KK) ? wproj[d * KK + kk + 1] : 0.f;
    g_bfrag[i] = packh2(w0, w1);
}

// ---------------------------------------------------------------------------
// Fused kernel: front pipeline (TILE=1000) + HMMA GEMM + LayerNorm + m_patch
// Dynamic smem layout (overlaid):
//   [0 .. 35840)        : sxr2 [2][1036] ull (0..16576) + sdx2 at 16640
//                          -> later reused as sB [8960] u32 (35840 B)
//   [36864 .. 53056)    : sS02 [2][1012] ull
//   [53248 .. 64768)    : sXh [48][120] half
//   [64768 .. 76288)    : sXl [48][120] half
// ---------------------------------------------------------------------------
#define OFF_SDX  16640
#define OFF_SS0  36864
#define OFF_XH   53248
#define OFF_XL   64768
#define DYN_SMEM 76288

__global__ __launch_bounds__(256, 2) void kernelF(
    const float* __restrict__ X, const float* __restrict__ Mv,
    const float* __restrict__ w_env, const float* __restrict__ w_burst,
    const float* __restrict__ syn, const float* __restrict__ w_dw,
    const float* __restrict__ w_pw, const float* __restrict__ gamma,
    const float* __restrict__ beta, float* __restrict__ out)
{
    extern __shared__ __align__(16) char dsm[];
    ull* sxr2 = (ull*)dsm;                       // [2][1036]
    ull* sdx2 = (ull*)(dsm + OFF_SDX);           // [2][1036]
    unsigned* sB = (unsigned*)dsm;               // overlays sxr2/sdx2 later
    ull* sS02 = (ull*)(dsm + OFF_SS0);           // [2][1012]
    __half* sXh = (__half*)(dsm + OFF_XH);       // [48][120]
    __half* sXl = (__half*)(dsm + OFF_XL);       // [48][120]

    __shared__ uchar4 smask[TILE];
    __shared__ unsigned char smt[TILE];
    __shared__ float sW[MS][Cc];
    __shared__ float sPW[MS][MS];
    __shared__ ull swe2[2][KE], swb2[2][KB], swd2[2][KP], sWsyn2[2][MS];
    __shared__ float sG[Dd], sBt[Dd];
    __shared__ float sSum[2][48], sSq[2][48];
    __shared__ float sMu[48], sRs[48];

    const int tid  = threadIdx.x;
    const int lane = tid & 31;
    const int wid  = tid >> 5;
    const int tile = blockIdx.x;
    const int b    = blockIdx.y;
    const int t0   = tile * TILE;
    const int Row0 = b * LL + tile * RPT;

    // ---- small weights ----
    if (tid < MS) {
        float v0 = softplus_f(syn[tid * Cc + 0]);
        float v1 = softplus_f(syn[tid * Cc + 1]);
        float v2 = softplus_f(syn[tid * Cc + 2]);
        float v3 = softplus_f(syn[tid * Cc + 3]);
        float s  = fmaxf(v0 + v1 + v2 + v3, 1e-6f);
        float inv = 1.0f / s;
        sW[tid][0] = v0 * inv; sW[tid][1] = v1 * inv;
        sW[tid][2] = v2 * inv; sW[tid][3] = v3 * inv;
    }
    if (tid >= 32 && tid < 32 + MS * MS) {
        int i = tid - 32;
        sPW[i / MS][i % MS] = w_pw[i];
    }
    for (int i = tid; i < Dd; i += 256) { sG[i] = gamma[i]; sBt[i] = beta[i]; }

    // ---- pass 1: raw masked x pairs + mask bytes ----
    const float4* X4 = (const float4*)(X + (size_t)b * Tt * Cc);
    const float4* M4 = (const float4*)(Mv + (size_t)b * Tt * Cc);
    for (int i = tid; i < TILE + 33; i += 256) {
        int t = t0 - 16 + i;
        float x0 = 0.f, x1 = 0.f, x2 = 0.f, x3 = 0.f;
        uchar4 mk = {0, 0, 0, 0};
        if (t >= 0 && t < Tt) {
            float4 a = X4[t], m = M4[t];
            x0 = a.x * m.x; x1 = a.y * m.y; x2 = a.z * m.z; x3 = a.w * m.w;
            mk.x = (m.x > 0.f); mk.y = (m.y > 0.f); mk.z = (m.z > 0.f); mk.w = (m.w > 0.f);
        }
        sxr2[i] = pack2(x0, x1);
        sxr2[NWIN + i] = pack2(x2, x3);
        int j = i - 16;
        if (j >= 0 && j < TILE) smask[j] = mk;
    }
    __syncthreads();

    // ---- weight pair packing + dx pass + zero sX pad ----
    if (tid < 2 * KE) {
        int cp = tid / KE, k = tid - cp * KE;
        swe2[cp][k] = pack2(w_env[(2 * cp) * KE + k], w_env[(2 * cp + 1) * KE + k]);
    } else if (tid >= 64 && tid < 64 + 2 * KB) {
        int i = tid - 64, cp = i / KB, k = i - cp * KB;
        swb2[cp][k] = pack2(w_burst[(2 * cp) * KB + k], w_burst[(2 * cp + 1) * KB + k]);
    } else if (tid >= 96 && tid < 96 + 2 * KP) {
        int i = tid - 96, p2 = i / KP, k = i - p2 * KP;
        swd2[p2][k] = pack2(w_dw[(2 * p2) * KP + k], w_dw[(2 * p2 + 1) * KP + k]);
    } else if (tid >= 128 && tid < 128 + 2 * MS) {
        int i = tid - 128, cp = i / MS, m = i - cp * MS;
        sWsyn2[cp][m] = pack2(sW[m][2 * cp], sW[m][2 * cp + 1]);
    }
    // zero sXh/sXl (48*120 halves each = 2880 u32 each)
    for (int i = tid; i < 2880; i += 256) {
        ((unsigned*)sXh)[i] = 0u;
        ((unsigned*)sXl)[i] = 0u;
    }
    for (int i = tid; i < TILE + 33; i += 256) {
        int tg = t0 - 16 + i;
        bool v = (tg >= 1) && (tg < Tt) && (i >= 1);
        ull d0 = 0, d1 = 0;
        if (v) {
            d0 = ffma2(sxr2[i - 1], NEG1P, sxr2[i]) & ABS2MASK;
            d1 = ffma2(sxr2[NWIN + i - 1], NEG1P, sxr2[NWIN + i]) & ABS2MASK;
        }
        sdx2[i] = d0;
        sdx2[NWIN + i] = d1;
    }
    __syncthreads();

    // ---- phase B: env/burst/xm -> S0 pairs; 1008 positions in 2 halves ----
    #pragma unroll 1
    for (int half = 0; half < 2; half++) {
        if (tid < 252) {
            const int j0 = half * 504 + tid * 2;
            ull accm[MS][2];
            #pragma unroll
            for (int m = 0; m < MS; m++) { accm[m][0] = 0ULL; accm[m][1] = 0ULL; }

            #pragma unroll
            for (int cp = 0; cp < 2; cp++) {
                const ull* xr = sxr2 + cp * NWIN;
                const ull* dx = sdx2 + cp * NWIN;
                ull wr[26];
                #pragma unroll
                for (int u = 0; u < 13; u++) {
                    F4U v; v.v = *(const float4*)&xr[j0 + 2 * u];
                    wr[2 * u] = v.u[0]; wr[2 * u + 1] = v.u[1];
                }
                ull xraw0 = wr[12], xraw1 = wr[13];
                #pragma unroll
                for (int u = 0; u < 26; u++) wr[u] &= ABS2MASK;

                ull env0 = 0ULL, env1 = 0ULL;
                #pragma unroll
                for (int k = 0; k < KE; k++) {
                    ull w = swe2[cp][k];
                    env0 = ffma2(wr[k], w, env0);
                    env1 = ffma2(wr[k + 1], w, env1);
                }
                ull da[10];
                #pragma unroll
                for (int u = 0; u < 5; u++) {
                    F4U v; v.v = *(const float4*)&dx[j0 + 8 + 2 * u];
                    da[2 * u] = v.u[0]; da[2 * u + 1] = v.u[1];
                }
                ull bur0 = 0ULL, bur1 = 0ULL;
                #pragma unroll
                for (int k = 0; k < KB; k++) {
                    ull w = swb2[cp][k];
                    bur0 = ffma2(da[k], w, bur0);
                    bur1 = ffma2(da[k + 1], w, bur1);
                }
                ull xm0 = ffma2(env0, C09P, ffma2(bur0, C06P, mul2(xraw0, C02P)));
                ull xm1 = ffma2(env1, C09P, ffma2(bur1, C06P, mul2(xraw1, C02P)));
                #pragma unroll
                for (int m = 0; m < MS; m++) {
                    ull w = sWsyn2[cp][m];
                    accm[m][0] = ffma2(xm0, w, accm[m][0]);
                    accm[m][1] = ffma2(xm1, w, accm[m][1]);
                }
            }
            #pragma unroll
            for (int p = 0; p < 2; p++) {
                int j  = j0 + p;
                int tp = t0 - 4 + j;
                bool valid = (tp >= 0 && tp < Tt);
                float s0[MS];
                #pragma unroll
                for (int m = 0; m < MS; m++) {
                    UF2 u; u.u = accm[m][p];
                    s0[m] = valid ? (u.f.x + u.f.y) : 0.f;
                }
                sS02[j] = pack2(s0[0], s0[1]);
                sS02[NS0 + j] = pack2(s0[2], s0[3]);
            }
        }
    }
    __syncthreads();
    // sxr2/sdx2 are now dead -> sB overlay region is free

    // ---- B-fragment copy into overlay ----
    {
        const uint4* src = (const uint4*)g_bfrag;
        uint4* dst = (uint4*)sB;
        for (int i = tid; i < BFRAG_U32 / 4; i += 256) dst[i] = src[i];
    }

    // ---- phase C: dwconv9+gelu, pointwise+gelu, mask, write sX fp16 hi/lo ----
    #pragma unroll 1
    for (int half = 0; half < 2; half++) {
        if (tid < 250) {
            const int i0 = half * 500 + tid * 2;
            float S1[2][MS];
            #pragma unroll
            for (int p2 = 0; p2 < 2; p2++) {
                const ull* s0p = sS02 + p2 * NS0;
                ull win[10];
                #pragma unroll
                for (int u = 0; u < 5; u++) {
                    F4U v; v.v = *(const float4*)&s0p[i0 + 2 * u];
                    win[2 * u] = v.u[0]; win[2 * u + 1] = v.u[1];
                }
                ull a0 = 0ULL, a1 = 0ULL;
                #pragma unroll
                for (int k = 0; k < KP; k++) {
                    ull w = swd2[p2][k];
                    a0 = ffma2(win[k], w, a0);
                    a1 = ffma2(win[k + 1], w, a1);
                }
                UF2 u0, u1; u0.u = a0; u1.u = a1;
                S1[0][2 * p2]     = gelu_exact(u0.f.x);
                S1[0][2 * p2 + 1] = gelu_exact(u0.f.y);
                S1[1][2 * p2]     = gelu_exact(u1.f.x);
                S1[1][2 * p2 + 1] = gelu_exact(u1.f.y);
            }
            #pragma unroll
            for (int pos = 0; pos < 2; pos++) {
                int i = i0 + pos;
                uchar4 mk = smask[i];
                float mf0 = (float)mk.x, mf1 = (float)mk.y, mf2 = (float)mk.z, mf3 = (float)mk.w;
                int l = i / PP, p = i - l * PP;
                float smsum = 0.f;
                #pragma unroll
                for (int o = 0; o < MS; o++) {
                    float a  = sPW[o][0] * S1[pos][0] + sPW[o][1] * S1[pos][1]
                             + sPW[o][2] * S1[pos][2] + sPW[o][3] * S1[pos][3];
                    float s2 = gelu_exact(a);
                    float sm = sW[o][0] * mf0 + sW[o][1] * mf1 + sW[o][2] * mf2 + sW[o][3] * mf3;
                    sm = fminf(fmaxf(sm, 0.f), 1.f);
                    smsum += sm;
                    float v = s2 * sm;
                    __half h = __float2half_rn(v);
                    int idx = l * XST + o * PP + p;
                    sXh[idx] = h;
                    sXl[idx] = __float2half_rn(v - __half2float(h));
                }
                smt[i] = (smsum > 0.f) ? 1 : 0;
            }
        }
    }
    __syncthreads();

    // ---- m_patch ----
    if (tid < RPT) {
        int s = 0;
        #pragma unroll
        for (int p = 0; p < PP; p++) s += smt[tid * PP + p];
        out[(size_t)HSIZE + Row0 + tid] = (s >= 3) ? 1.f : 0.f;
    }

    // ---- HMMA mainloop: warps 0-5 (3 rg x 2 nh), 2 passes ----
    float acc[10][4];
    #pragma unroll
    for (int n = 0; n < 10; n++)
        #pragma unroll
        for (int j = 0; j < 4; j++) acc[n][j] = 0.f;

    const int rg = wid >> 1;
    const int nh = wid & 1;

    if (wid < 6) {
        const int row0 = rg * 16 + (lane >> 2);
        #pragma unroll
        for (int p = 0; p < 2; p++) {
            const __half* sX = p ? sXl : sXh;
            #pragma unroll
            for (int kc = 0; kc < NKC; kc++) {
                int c0 = kc * 16 + (lane & 3) * 2;
                unsigned a0 = *(const unsigned*)&sX[row0 * XST + c0];
                unsigned a1 = *(const unsigned*)&sX[(row0 + 8) * XST + c0];
                unsigned a2 = *(const unsigned*)&sX[row0 * XST + c0 + 8];
                unsigned a3 = *(const unsigned*)&sX[(row0 + 8) * XST + c0 + 8];
                #pragma unroll
                for (int n = 0; n < 10; n++) {
                    int nn = nh * 10 + n;
                    uint2 bf = *(const uint2*)&sB[(kc * NNC + nn) * 64 + lane * 2];
                    hmma16816(acc[n][0], acc[n][1], acc[n][2], acc[n][3],
                              a0, a1, a2, a3, bf.x, bf.y);
                }
            }
        }

        // ---- LN partial moments (quad reduce) ----
        float sL = 0.f, qL = 0.f, sH = 0.f, qH = 0.f;
        #pragma unroll
        for (int n = 0; n < 10; n++) {
            sL += acc[n][0] + acc[n][1];
            qL += acc[n][0] * acc[n][0] + acc[n][1] * acc[n][1];
            sH += acc[n][2] + acc[n][3];
            qH += acc[n][2] * acc[n][2] + acc[n][3] * acc[n][3];
        }
        #pragma unroll
        for (int off = 1; off <= 2; off <<= 1) {
            sL += __shfl_xor_sync(0xFFFFFFFFu, sL, off);
            qL += __shfl_xor_sync(0xFFFFFFFFu, qL, off);
            sH += __shfl_xor_sync(0xFFFFFFFFu, sH, off);
            qH += __shfl_xor_sync(0xFFFFFFFFu, qH, off);
        }
        int rl0 = rg * 16 + (lane >> 2);
        if ((lane & 3) == 0) {
            sSum[nh][rl0] = sL; sSq[nh][rl0] = qL;
            if (rl0 + 8 < 48) { sSum[nh][rl0 + 8] = sH; sSq[nh][rl0 + 8] = qH; }
        }
    }
    __syncthreads();

    if (tid < RPT) {
        float s = sSum[0][tid] + sSum[1][tid];
        float q = sSq[0][tid] + sSq[1][tid];
        float mu  = s * (1.0f / Dd);
        float var = q * (1.0f / Dd) - mu * mu;
        sMu[tid] = mu;
        sRs[tid] = rsqrtf(var + 1e-5f);
    }
    __syncthreads();

    if (wid < 6) {
        int rl0 = rg * 16 + (lane >> 2);
        int rHi = rl0 + 8;
        float muL = sMu[rl0], rsL = sRs[rl0];
        bool hasH = (rHi < RPT);
        float muH = hasH ? sMu[rHi] : 0.f;
        float rsH = hasH ? sRs[rHi] : 0.f;
        float* outL = out + (size_t)(Row0 + rl0) * Dd;
        float* outH = out + (size_t)(Row0 + rHi) * Dd;
        #pragma unroll
        for (int n = 0; n < 10; n++) {
            int col = (nh * 10 + n) * 8 + (lane & 3) * 2;
            float2 g = *(const float2*)&sG[col];
            float2 bt = *(const float2*)&sBt[col];
            float2 v0;
            v0.x = (acc[n][0] - muL) * rsL * g.x + bt.x;
            v0.y = (acc[n][1] - muL) * rsL * g.y + bt.y;
            *(float2*)(outL + col) = v0;
            if (hasH) {
                float2 v1;
                v1.x = (acc[n][2] - muH) * rsH * g.x + bt.x;
                v1.y = (acc[n][3] - muH) * rsH * g.y + bt.y;
                *(float2*)(outH + col) = v1;
            }
        }
    }
}

// ---------------------------------------------------------------------------
extern "C" void kernel_launch(void* const* d_in, const int* in_sizes, int n_in,
                              void* d_out, int out_size)
{
    const float* X      = (const float*)d_in[0];
    const float* M      = (const float*)d_in[1];
    const float* w_env  = (const float*)d_in[2];
    const float* w_bur  = (const float*)d_in[3];
    const float* syn    = (const float*)d_in[4];
    const float* w_dw   = (const float*)d_in[5];
    const float* w_pw   = (const float*)d_in[6];
    const float* w_proj = (const float*)d_in[7];
    const float* gamma  = (const float*)d_in[8];
    const float* beta   = (const float*)d_in[9];
    float* out = (float*)d_out;

    cudaFuncSetAttribute(kernelF, cudaFuncAttributeMaxDynamicSharedMemorySize, DYN_SMEM);

    kernelW<<<(BFRAG_U32 + 255) / 256, 256>>>(w_proj);
    dim3 gF(NT, Bb);
    kernelF<<<gF, 256, DYN_SMEM>>>(X, M, w_env, w_bur, syn, w_dw, w_pw,
                                   gamma, beta, out);
}

// round 10
// speedup vs baseline: 1.5368x; 1.1390x over previous
#include <cuda_runtime.h>
#include <cuda_fp16.h>
#include <math.h>
#include <cstdint>

#define Bb 64
#define Tt 50000
#define Cc 4
#define MS 4
#define Dd 160
#define PP 25
#define KE 25
#define KB 9
#define KP 9
#define LL 2000
#define TILE 500
#define NT (Tt / TILE)          // 100
#define RPT (TILE / PP)         // 20 rows per tile
#define HSIZE (Bb * LL * Dd)
#define KK 100
#define NWIN 536
#define NS0 512
#define XST 120                 // sX stride in halves (k pad 112 + 8)
#define XROWS 32

// precomputed W Bh-fragments (fp16): [kc 7][nn 20][lane 32][rb 2] u32
#define NKC 7
#define NNC 20
#define BFRAG_U32 (NKC * NNC * 64)
__device__ unsigned g_bfrag[BFRAG_U32];

typedef unsigned long long ull;

__device__ __forceinline__ float gelu_exact(float v) {
    return 0.5f * v * (1.0f + erff(v * 0.70710678118654752f));
}
__device__ __forceinline__ float softplus_f(float v) {
    return fmaxf(v, 0.0f) + log1pf(expf(-fabsf(v)));
}
__device__ __forceinline__ ull ffma2(ull a, ull b, ull c) {
    ull d;
    asm("fma.rn.f32x2 %0, %1, %2, %3;" : "=l"(d) : "l"(a), "l"(b), "l"(c));
    return d;
}
__device__ __forceinline__ ull mul2(ull a, ull b) {
    ull d;
    asm("mul.rn.f32x2 %0, %1, %2;" : "=l"(d) : "l"(a), "l"(b));
    return d;
}
__device__ __forceinline__ ull pack2(float x, float y) {
    ull d;
    asm("mov.b64 %0, {%1, %2};" : "=l"(d) : "f"(x), "f"(y));
    return d;
}
union F4U { float4 v; ull u[2]; };
union UF2 { ull u; float2 f; };

#define ABS2MASK 0x7FFFFFFF7FFFFFFFULL
#define NEG1P    0xBF800000BF800000ULL
#define C09P     0x3F6666663F666666ULL
#define C06P     0x3F19999A3F19999AULL
#define C02P     0x3E4CCCCD3E4CCCCDULL

__device__ __forceinline__ unsigned packh2(float a, float b) {
    __half2 t = __floats2half2_rn(a, b);
    return *reinterpret_cast<unsigned*>(&t);
}

__device__ __forceinline__ void hmma16816(
    float& c0, float& c1, float& c2, float& c3,
    unsigned a0, unsigned a1, unsigned a2, unsigned a3,
    unsigned b0, unsigned b1)
{
    asm volatile(
        "mma.sync.aligned.m16n8k16.row.col.f32.f16.f16.f32 "
        "{%0,%1,%2,%3}, {%4,%5,%6,%7}, {%8,%9}, {%0,%1,%2,%3};"
        : "+f"(c0), "+f"(c1), "+f"(c2), "+f"(c3)
        : "r"(a0), "r"(a1), "r"(a2), "r"(a3), "r"(b0), "r"(b1));
}

// ---------------------------------------------------------------------------
// Kernel W: precompute fp16 B-fragments of wproj for m16n8k16 HMMA.
// ---------------------------------------------------------------------------
__global__ void kernelW(const float* __restrict__ wproj) {
    int i = blockIdx.x * 256 + threadIdx.x;
    if (i >= BFRAG_U32) return;
    int kc  = i / (NNC * 64);
    int r2  = i % (NNC * 64);
    int nn  = r2 / 64;
    int q   = r2 % 64;
    int lane = q >> 1, rb = q & 1;
    int d  = nn * 8 + (lane >> 2);
    int kk = kc * 16 + (lane & 3) * 2 + rb * 8;
    float w0 = (kk < KK) ? wproj[d * KK + kk] : 0.f;
    float w1 = (kk < KK) ? wproj[d * KK + kk + 1] : 0.f;
    g_bfrag[i] = packh2(w0, w1);
}

// ---------------------------------------------------------------------------
// Fused kernel, TILE=500, 3 blocks/SM target.
// Dynamic smem layout (overlaid):
//   [0 .. 17152)     sxr2 [2][536] ull (0..8576) + sdx2 (8576..17152)
//                    -> after phase B reused as sB [8960] u32 (0..35840)
//   [35840 .. 44032) sS02 [2][512] ull  -> after HMMA reused as scratch
//   [44032 .. 51712) sXh [32][120] half
//   [51712 .. 59392) sXl [32][120] half
// scratch (pass-combine): [35840 .. 58368) floats [4][32][44]
// ---------------------------------------------------------------------------
#define OFF_SDX  8576
#define OFF_SS0  35840
#define OFF_XH   44032
#define OFF_XL   51712
#define OFF_SCR  35840
#define DYN_SMEM 59392

__global__ __launch_bounds__(256, 3) void kernelF(
    const float* __restrict__ X, const float* __restrict__ Mv,
    const float* __restrict__ w_env, const float* __restrict__ w_burst,
    const float* __restrict__ syn, const float* __restrict__ w_dw,
    const float* __restrict__ w_pw, const float* __restrict__ gamma,
    const float* __restrict__ beta, float* __restrict__ out)
{
    extern __shared__ __align__(16) char dsm[];
    ull* sxr2 = (ull*)dsm;                       // [2][536]
    ull* sdx2 = (ull*)(dsm + OFF_SDX);           // [2][536]
    unsigned* sB = (unsigned*)dsm;               // overlays after phase B
    ull* sS02 = (ull*)(dsm + OFF_SS0);           // [2][512]
    __half* sXh = (__half*)(dsm + OFF_XH);       // [32][120]
    __half* sXl = (__half*)(dsm + OFF_XL);       // [32][120]

    __shared__ uchar4 smask[TILE];
    __shared__ unsigned char smt[TILE];
    __shared__ float sW[MS][Cc];
    __shared__ float sPW[MS][MS];
    __shared__ ull swe2[2][KE], swb2[2][KB], swd2[2][KP], sWsyn2[2][MS];
    __shared__ float sG[Dd], sBt[Dd];
    __shared__ float sSum[2][XROWS], sSq[2][XROWS];
    __shared__ float sMu[RPT], sRs[RPT];

    const int tid  = threadIdx.x;
    const int lane = tid & 31;
    const int wid  = tid >> 5;
    const int tile = blockIdx.x;
    const int b    = blockIdx.y;
    const int t0   = tile * TILE;
    const int Row0 = b * LL + tile * RPT;

    // ---- small weights ----
    if (tid < MS) {
        float v0 = softplus_f(syn[tid * Cc + 0]);
        float v1 = softplus_f(syn[tid * Cc + 1]);
        float v2 = softplus_f(syn[tid * Cc + 2]);
        float v3 = softplus_f(syn[tid * Cc + 3]);
        float s  = fmaxf(v0 + v1 + v2 + v3, 1e-6f);
        float inv = 1.0f / s;
        sW[tid][0] = v0 * inv; sW[tid][1] = v1 * inv;
        sW[tid][2] = v2 * inv; sW[tid][3] = v3 * inv;
    }
    if (tid >= 32 && tid < 32 + MS * MS) {
        int i = tid - 32;
        sPW[i / MS][i % MS] = w_pw[i];
    }
    for (int i = tid; i < Dd; i += 256) { sG[i] = gamma[i]; sBt[i] = beta[i]; }

    // ---- pass 1: raw masked x pairs + mask bytes ----
    const float4* X4 = (const float4*)(X + (size_t)b * Tt * Cc);
    const float4* M4 = (const float4*)(Mv + (size_t)b * Tt * Cc);
    for (int i = tid; i < TILE + 33; i += 256) {
        int t = t0 - 16 + i;
        float x0 = 0.f, x1 = 0.f, x2 = 0.f, x3 = 0.f;
        uchar4 mk = {0, 0, 0, 0};
        if (t >= 0 && t < Tt) {
            float4 a = X4[t], m = M4[t];
            x0 = a.x * m.x; x1 = a.y * m.y; x2 = a.z * m.z; x3 = a.w * m.w;
            mk.x = (m.x > 0.f); mk.y = (m.y > 0.f); mk.z = (m.z > 0.f); mk.w = (m.w > 0.f);
        }
        sxr2[i] = pack2(x0, x1);
        sxr2[NWIN + i] = pack2(x2, x3);
        int j = i - 16;
        if (j >= 0 && j < TILE) smask[j] = mk;
    }
    __syncthreads();

    // ---- weight pair packing + dx pass + zero sX ----
    if (tid < 2 * KE) {
        int cp = tid / KE, k = tid - cp * KE;
        swe2[cp][k] = pack2(w_env[(2 * cp) * KE + k], w_env[(2 * cp + 1) * KE + k]);
    } else if (tid >= 64 && tid < 64 + 2 * KB) {
        int i = tid - 64, cp = i / KB, k = i - cp * KB;
        swb2[cp][k] = pack2(w_burst[(2 * cp) * KB + k], w_burst[(2 * cp + 1) * KB + k]);
    } else if (tid >= 96 && tid < 96 + 2 * KP) {
        int i = tid - 96, p2 = i / KP, k = i - p2 * KP;
        swd2[p2][k] = pack2(w_dw[(2 * p2) * KP + k], w_dw[(2 * p2 + 1) * KP + k]);
    } else if (tid >= 128 && tid < 128 + 2 * MS) {
        int i = tid - 128, cp = i / MS, m = i - cp * MS;
        sWsyn2[cp][m] = pack2(sW[m][2 * cp], sW[m][2 * cp + 1]);
    }
    for (int i = tid; i < XROWS * XST / 2; i += 256) {
        ((unsigned*)sXh)[i] = 0u;
        ((unsigned*)sXl)[i] = 0u;
    }
    for (int i = tid; i < TILE + 33; i += 256) {
        int tg = t0 - 16 + i;
        bool v = (tg >= 1) && (tg < Tt) && (i >= 1);
        ull d0 = 0, d1 = 0;
        if (v) {
            d0 = ffma2(sxr2[i - 1], NEG1P, sxr2[i]) & ABS2MASK;
            d1 = ffma2(sxr2[NWIN + i - 1], NEG1P, sxr2[NWIN + i]) & ABS2MASK;
        }
        sdx2[i] = d0;
        sdx2[NWIN + i] = d1;
    }
    __syncthreads();

    // ---- phase B: rolling-window env/burst/xm -> S0 pairs ----
    if (tid < 254) {
        const int j0 = tid * 2;
        ull accm[MS][2];
        #pragma unroll
        for (int m = 0; m < MS; m++) { accm[m][0] = 0ULL; accm[m][1] = 0ULL; }

        #pragma unroll
        for (int cp = 0; cp < 2; cp++) {
            const ull* xr = sxr2 + cp * NWIN;
            const ull* dx = sdx2 + cp * NWIN;
            ull env0 = 0ULL, env1 = 0ULL, xraw0 = 0ULL, xraw1 = 0ULL;
            #pragma unroll
            for (int u = 0; u < 13; u++) {
                F4U v; v.v = *(const float4*)&xr[j0 + 2 * u];
                if (u == 6) { xraw0 = v.u[0]; xraw1 = v.u[1]; }
                ull p0 = v.u[0] & ABS2MASK;
                ull p1 = v.u[1] & ABS2MASK;
                const int k0 = 2 * u;
                if (k0 <= 24)     env0 = ffma2(p0, swe2[cp][k0], env0);
                if (k0 + 1 <= 24) env0 = ffma2(p1, swe2[cp][k0 + 1], env0);
                if (k0 >= 1)      env1 = ffma2(p0, swe2[cp][k0 - 1], env1);
                if (k0 <= 24)     env1 = ffma2(p1, swe2[cp][k0], env1);
            }
            ull bur0 = 0ULL, bur1 = 0ULL;
            #pragma unroll
            for (int u = 0; u < 5; u++) {
                F4U v; v.v = *(const float4*)&dx[j0 + 8 + 2 * u];
                const int k0 = 2 * u;
                if (k0 <= 8)     bur0 = ffma2(v.u[0], swb2[cp][k0], bur0);
                if (k0 + 1 <= 8) bur0 = ffma2(v.u[1], swb2[cp][k0 + 1], bur0);
                if (k0 >= 1)     bur1 = ffma2(v.u[0], swb2[cp][k0 - 1], bur1);
                if (k0 <= 8)     bur1 = ffma2(v.u[1], swb2[cp][k0], bur1);
            }
            ull xm0 = ffma2(env0, C09P, ffma2(bur0, C06P, mul2(xraw0, C02P)));
            ull xm1 = ffma2(env1, C09P, ffma2(bur1, C06P, mul2(xraw1, C02P)));
            #pragma unroll
            for (int m = 0; m < MS; m++) {
                ull w = sWsyn2[cp][m];
                accm[m][0] = ffma2(xm0, w, accm[m][0]);
                accm[m][1] = ffma2(xm1, w, accm[m][1]);
            }
        }
        #pragma unroll
        for (int p = 0; p < 2; p++) {
            int j  = j0 + p;
            int tp = t0 - 4 + j;
            bool valid = (tp >= 0 && tp < Tt);
            float s0[MS];
            #pragma unroll
            for (int m = 0; m < MS; m++) {
                UF2 u; u.u = accm[m][p];
                s0[m] = valid ? (u.f.x + u.f.y) : 0.f;
            }
            sS02[j] = pack2(s0[0], s0[1]);
            sS02[NS0 + j] = pack2(s0[2], s0[3]);
        }
    }
    __syncthreads();
    // sxr2/sdx2 dead -> sB overlay free

    // ---- B-fragment copy into overlay ----
    {
        const uint4* src = (const uint4*)g_bfrag;
        uint4* dst = (uint4*)sB;
        for (int i = tid; i < BFRAG_U32 / 4; i += 256) dst[i] = src[i];
    }

    // ---- phase C: rolling dwconv9+gelu, pointwise+gelu, write sX fp16 hi/lo ----
    if (tid < 250) {
        const int i0 = tid * 2;
        float S1[2][MS];
        #pragma unroll
        for (int p2 = 0; p2 < 2; p2++) {
            const ull* s0p = sS02 + p2 * NS0;
            ull a0 = 0ULL, a1 = 0ULL;
            #pragma unroll
            for (int u = 0; u < 5; u++) {
                F4U v; v.v = *(const float4*)&s0p[i0 + 2 * u];
                const int k0 = 2 * u;
                if (k0 <= 8)     a0 = ffma2(v.u[0], swd2[p2][k0], a0);
                if (k0 + 1 <= 8) a0 = ffma2(v.u[1], swd2[p2][k0 + 1], a0);
                if (k0 >= 1)     a1 = ffma2(v.u[0], swd2[p2][k0 - 1], a1);
                if (k0 <= 8)     a1 = ffma2(v.u[1], swd2[p2][k0], a1);
            }
            UF2 u0, u1; u0.u = a0; u1.u = a1;
            S1[0][2 * p2]     = gelu_exact(u0.f.x);
            S1[0][2 * p2 + 1] = gelu_exact(u0.f.y);
            S1[1][2 * p2]     = gelu_exact(u1.f.x);
            S1[1][2 * p2 + 1] = gelu_exact(u1.f.y);
        }
        #pragma unroll
        for (int pos = 0; pos < 2; pos++) {
            int i = i0 + pos;
            uchar4 mk = smask[i];
            float mf0 = (float)mk.x, mf1 = (float)mk.y, mf2 = (float)mk.z, mf3 = (float)mk.w;
            int l = i / PP, p = i - l * PP;
            float smsum = 0.f;
            #pragma unroll
            for (int o = 0; o < MS; o++) {
                float a  = sPW[o][0] * S1[pos][0] + sPW[o][1] * S1[pos][1]
                         + sPW[o][2] * S1[pos][2] + sPW[o][3] * S1[pos][3];
                float s2 = gelu_exact(a);
                float sm = sW[o][0] * mf0 + sW[o][1] * mf1 + sW[o][2] * mf2 + sW[o][3] * mf3;
                sm = fminf(fmaxf(sm, 0.f), 1.f);
                smsum += sm;
                float v = s2 * sm;
                __half h = __float2half_rn(v);
                int idx = l * XST + o * PP + p;
                sXh[idx] = h;
                sXl[idx] = __float2half_rn(v - __half2float(h));
            }
            smt[i] = (smsum > 0.f) ? 1 : 0;
        }
    }
    __syncthreads();

    // ---- m_patch ----
    if (tid < RPT) {
        int s = 0;
        #pragma unroll
        for (int p = 0; p < PP; p++) s += smt[tid * PP + p];
        out[(size_t)HSIZE + Row0 + tid] = (s >= 3) ? 1.f : 0.f;
    }

    // ---- HMMA mainloop: all 8 warps, pass-split ----
    const int pss = wid >> 2;          // 0 = hi, 1 = lo
    const int rg  = (wid >> 1) & 1;    // row-group (m16)
    const int nh  = wid & 1;           // n-half
    const int row0 = rg * 16 + (lane >> 2);

    float acc[10][4];
    #pragma unroll
    for (int n = 0; n < 10; n++)
        #pragma unroll
        for (int j = 0; j < 4; j++) acc[n][j] = 0.f;

    {
        const __half* sX = pss ? sXl : sXh;
        #pragma unroll
        for (int kc = 0; kc < NKC; kc++) {
            int c0 = kc * 16 + (lane & 3) * 2;
            unsigned a0 = *(const unsigned*)&sX[row0 * XST + c0];
            unsigned a1 = *(const unsigned*)&sX[(row0 + 8) * XST + c0];
            unsigned a2 = *(const unsigned*)&sX[row0 * XST + c0 + 8];
            unsigned a3 = *(const unsigned*)&sX[(row0 + 8) * XST + c0 + 8];
            #pragma unroll
            for (int n = 0; n < 10; n++) {
                int nn = nh * 10 + n;
                uint2 bf = *(const uint2*)&sB[(kc * NNC + nn) * 64 + lane * 2];
                hmma16816(acc[n][0], acc[n][1], acc[n][2], acc[n][3],
                          a0, a1, a2, a3, bf.x, bf.y);
            }
        }
    }
    __syncthreads();   // sX/sS02 dead; scratch region safe to write

    float* scr = (float*)(dsm + OFF_SCR);   // [4 tiles][32 lanes][44]
    if (pss == 1) {
        float* d = scr + ((rg * 2 + nh) * 32 + lane) * 44;
        #pragma unroll
        for (int n = 0; n < 10; n++)
            *(float4*)&d[n * 4] = make_float4(acc[n][0], acc[n][1], acc[n][2], acc[n][3]);
    }
    __syncthreads();
    if (pss == 0) {
        const float* d = scr + ((rg * 2 + nh) * 32 + lane) * 44;
        #pragma unroll
        for (int n = 0; n < 10; n++) {
            float4 v = *(const float4*)&d[n * 4];
            acc[n][0] += v.x; acc[n][1] += v.y; acc[n][2] += v.z; acc[n][3] += v.w;
        }
        // ---- LN partial moments (quad reduce) ----
        float sL = 0.f, qL = 0.f, sH = 0.f, qH = 0.f;
        #pragma unroll
        for (int n = 0; n < 10; n++) {
            sL += acc[n][0] + acc[n][1];
            qL += acc[n][0] * acc[n][0] + acc[n][1] * acc[n][1];
            sH += acc[n][2] + acc[n][3];
            qH += acc[n][2] * acc[n][2] + acc[n][3] * acc[n][3];
        }
        #pragma unroll
        for (int off = 1; off <= 2; off <<= 1) {
            sL += __shfl_xor_sync(0xFFFFFFFFu, sL, off);
            qL += __shfl_xor_sync(0xFFFFFFFFu, qL, off);
            sH += __shfl_xor_sync(0xFFFFFFFFu, sH, off);
            qH += __shfl_xor_sync(0xFFFFFFFFu, qH, off);
        }
        if ((lane & 3) == 0) {
            sSum[nh][row0] = sL; sSq[nh][row0] = qL;
            sSum[nh][row0 + 8] = sH; sSq[nh][row0 + 8] = qH;
        }
    }
    __syncthreads();

    if (tid < RPT) {
        float s = sSum[0][tid] + sSum[1][tid];
        float q = sSq[0][tid] + sSq[1][tid];
        float mu  = s * (1.0f / Dd);
        float var = q * (1.0f / Dd) - mu * mu;
        sMu[tid] = mu;
        sRs[tid] = rsqrtf(var + 1e-5f);
    }
    __syncthreads();

    if (pss == 0) {
        const int rHi = row0 + 8;
        const bool hasL = (row0 < RPT);
        const bool hasH = (rHi < RPT);
        float muL = hasL ? sMu[row0] : 0.f;
        float rsL = hasL ? sRs[row0] : 0.f;
        float muH = hasH ? sMu[rHi] : 0.f;
        float rsH = hasH ? sRs[rHi] : 0.f;
        float* outL = out + (size_t)(Row0 + row0) * Dd;
        float* outH = out + (size_t)(Row0 + rHi) * Dd;
        #pragma unroll
        for (int n = 0; n < 10; n++) {
            int col = (nh * 10 + n) * 8 + (lane & 3) * 2;
            float2 g = *(const float2*)&sG[col];
            float2 bt = *(const float2*)&sBt[col];
            if (hasL) {
                float2 v0;
                v0.x = (acc[n][0] - muL) * rsL * g.x + bt.x;
                v0.y = (acc[n][1] - muL) * rsL * g.y + bt.y;
                *(float2*)(outL + col) = v0;
            }
            if (hasH) {
                float2 v1;
                v1.x = (acc[n][2] - muH) * rsH * g.x + bt.x;
                v1.y = (acc[n][3] - muH) * rsH * g.y + bt.y;
                *(float2*)(outH + col) = v1;
            }
        }
    }
}

// ---------------------------------------------------------------------------
extern "C" void kernel_launch(void* const* d_in, const int* in_sizes, int n_in,
                              void* d_out, int out_size)
{
    const float* X      = (const float*)d_in[0];
    const float* M      = (const float*)d_in[1];
    const float* w_env  = (const float*)d_in[2];
    const float* w_bur  = (const float*)d_in[3];
    const float* syn    = (const float*)d_in[4];
    const float* w_dw   = (const float*)d_in[5];
    const float* w_pw   = (const float*)d_in[6];
    const float* w_proj = (const float*)d_in[7];
    const float* gamma  = (const float*)d_in[8];
    const float* beta   = (const float*)d_in[9];
    float* out = (float*)d_out;

    cudaFuncSetAttribute(kernelF, cudaFuncAttributeMaxDynamicSharedMemorySize, DYN_SMEM);

    kernelW<<<(BFRAG_U32 + 255) / 256, 256>>>(w_proj);
    dim3 gF(NT, Bb);
    kernelF<<<gF, 256, DYN_SMEM>>>(X, M, w_env, w_bur, syn, w_dw, w_pw,
                                   gamma, beta, out);
}